// round 2
// baseline (speedup 1.0000x reference)
#include <cuda_runtime.h>
#include <math.h>

#define B_  4
#define T_  2048
#define D_  1024
#define H_  16
#define HD_ 64
#define BT_ (B_ * T_)

// Scratch for Q, K, V projections (device globals: no allocation, capture-safe)
__device__ float g_q[(size_t)BT_ * D_];
__device__ float g_k[(size_t)BT_ * D_];
__device__ float g_v[(size_t)BT_ * D_];

// ---------------------------------------------------------------------------
// Kernel 1: y = x @ W^T for W in {Wq, Wk, Wv}  (blockIdx.z selects)
// x: [8192, 1024] row-major, W: [1024, 1024] row-major (y[m,n] = sum_k x[m,k]*W[n,k])
// BM=BN=64, BK=32, 256 threads, 4x4 micro-tile.
// Smem tiles stored k-major with stride 65: conflict-free loads and stores.
// ---------------------------------------------------------------------------
__global__ __launch_bounds__(256) void qkv_gemm(
    const float* __restrict__ x,
    const float* __restrict__ Wq,
    const float* __restrict__ Wk,
    const float* __restrict__ Wv)
{
    const float* W = (blockIdx.z == 0) ? Wq : ((blockIdx.z == 1) ? Wk : Wv);
    float* y = (blockIdx.z == 0) ? g_q : ((blockIdx.z == 1) ? g_k : g_v);

    __shared__ float Ast[32 * 65];  // [k][m], stride 65
    __shared__ float Bst[32 * 65];  // [k][n], stride 65

    const int tid = threadIdx.x;
    const int tx = tid & 15;        // 0..15 -> n micro
    const int ty = tid >> 4;        // 0..15 -> m micro
    const int m0 = blockIdx.y * 64;
    const int n0 = blockIdx.x * 64;

    float acc[4][4];
#pragma unroll
    for (int i = 0; i < 4; i++)
#pragma unroll
        for (int j = 0; j < 4; j++) acc[i][j] = 0.0f;

    for (int k0 = 0; k0 < D_; k0 += 32) {
        // 64x32 tile: 2048 elements, 256 threads -> 8 each.
        // Global reads coalesced (c consecutive); smem writes stride-65 (conflict-free).
#pragma unroll
        for (int i = tid; i < 64 * 32; i += 256) {
            int r = i >> 5;          // 0..63 (m or n)
            int c = i & 31;          // 0..31 (k)
            Ast[c * 65 + r] = x[(size_t)(m0 + r) * D_ + k0 + c];
            Bst[c * 65 + r] = W[(size_t)(n0 + r) * D_ + k0 + c];
        }
        __syncthreads();
#pragma unroll
        for (int kk = 0; kk < 32; kk++) {
            float a[4], b[4];
#pragma unroll
            for (int i = 0; i < 4; i++) a[i] = Ast[kk * 65 + ty * 4 + i];
#pragma unroll
            for (int j = 0; j < 4; j++) b[j] = Bst[kk * 65 + tx * 4 + j];
#pragma unroll
            for (int i = 0; i < 4; i++)
#pragma unroll
                for (int j = 0; j < 4; j++) acc[i][j] = fmaf(a[i], b[j], acc[i][j]);
        }
        __syncthreads();
    }

#pragma unroll
    for (int i = 0; i < 4; i++)
#pragma unroll
        for (int j = 0; j < 4; j++)
            y[(size_t)(m0 + ty * 4 + i) * D_ + n0 + tx * 4 + j] = acc[i][j];
}

// ---------------------------------------------------------------------------
// Kernel 2: palace-masked flash attention.
// Grid: (T/64 q-tiles, B*H). Block: 256 threads (16x16, 4x4 micro-tiles).
// Smem: Qt [64][65] d-major, Kt [64][65] d-major (reused as P [row][key]),
//       Vs [64][64] key-major. All accesses conflict-free.
// Mask is a fixed 64x64 pattern (tiles are 64-aligned): intra 8-block -> 1,
// else sigmoid(w). Folded with scale into per-thread constants.
// ---------------------------------------------------------------------------
#define SMEM_FLOATS (64 * 65 + 64 * 65 + 64 * 64)
#define SMEM_BYTES  (SMEM_FLOATS * 4)

__global__ __launch_bounds__(256) void palace_attn(
    const float* __restrict__ wp, float* __restrict__ out)
{
    extern __shared__ float sm[];
    float* Qt = sm;                // 64*65, [d][row]
    float* Kt = Qt + 64 * 65;      // 64*65, [d][key]; reused as P [row][key] stride 65
    float* Vs = Kt + 64 * 65;      // 64*64, [key][hd]

    const int tid = threadIdx.x;
    const int tx = tid & 15;       // key / hd micro
    const int ty = tid >> 4;       // q-row micro
    const int qt = blockIdx.x;
    const int bh = blockIdx.y;
    const int b = bh >> 4;
    const int h = bh & 15;

    const float sigw  = 1.0f / (1.0f + __expf(-wp[0]));
    const float scale = 0.125f;    // hd^-0.5, hd=64

    const size_t base = (size_t)b * T_ * D_ + (size_t)h * HD_;
    const float* qptr = g_q + base + (size_t)qt * 64 * D_;

    // Load Q tile transposed: read coalesced, write stride-65 (conflict-free)
#pragma unroll
    for (int i = tid; i < 64 * 64; i += 256) {
        int r = i >> 6, c = i & 63;
        Qt[c * 65 + r] = qptr[(size_t)r * D_ + c];
    }

    // mask*scale per thread (depends only on in-tile indices; tiles 64-aligned)
    float mw[4][4];
#pragma unroll
    for (int i = 0; i < 4; i++)
#pragma unroll
        for (int j = 0; j < 4; j++)
            mw[i][j] = (((ty * 4 + i) >> 3) == ((tx * 4 + j) >> 3)) ? scale : scale * sigw;

    float m_i[4], l_i[4], acc[4][4];
#pragma unroll
    for (int i = 0; i < 4; i++) {
        m_i[i] = -1e30f;
        l_i[i] = 0.0f;
#pragma unroll
        for (int j = 0; j < 4; j++) acc[i][j] = 0.0f;
    }

    __syncthreads();

    for (int kt = 0; kt < T_ / 64; kt++) {
        const float* kptr = g_k + base + (size_t)kt * 64 * D_;
        const float* vptr = g_v + base + (size_t)kt * 64 * D_;
#pragma unroll
        for (int i = tid; i < 64 * 64; i += 256) {
            int r = i >> 6, c = i & 63;
            Kt[c * 65 + r]  = kptr[(size_t)r * D_ + c];   // transposed
            Vs[r * 64 + c]  = vptr[(size_t)r * D_ + c];   // row-major
        }
        __syncthreads();

        // S = Q @ K^T  (64x64), 4x4 micro-tile per thread
        float s[4][4];
#pragma unroll
        for (int i = 0; i < 4; i++)
#pragma unroll
            for (int j = 0; j < 4; j++) s[i][j] = 0.0f;
#pragma unroll
        for (int kk = 0; kk < 64; kk++) {
            float a[4], bb[4];
#pragma unroll
            for (int i = 0; i < 4; i++) a[i] = Qt[kk * 65 + ty * 4 + i];
#pragma unroll
            for (int j = 0; j < 4; j++) bb[j] = Kt[kk * 65 + tx * 4 + j];
#pragma unroll
            for (int i = 0; i < 4; i++)
#pragma unroll
                for (int j = 0; j < 4; j++) s[i][j] = fmaf(a[i], bb[j], s[i][j]);
        }
#pragma unroll
        for (int i = 0; i < 4; i++)
#pragma unroll
            for (int j = 0; j < 4; j++) s[i][j] *= mw[i][j];

        // Online softmax: row reductions across the 16 lanes sharing ty
        float p[4][4];
#pragma unroll
        for (int i = 0; i < 4; i++) {
            float mx = s[i][0];
#pragma unroll
            for (int j = 1; j < 4; j++) mx = fmaxf(mx, s[i][j]);
#pragma unroll
            for (int o = 8; o >= 1; o >>= 1)
                mx = fmaxf(mx, __shfl_xor_sync(0xffffffffu, mx, o));
            float mnew = fmaxf(m_i[i], mx);
            float rs = 0.0f;
#pragma unroll
            for (int j = 0; j < 4; j++) { p[i][j] = __expf(s[i][j] - mnew); rs += p[i][j]; }
#pragma unroll
            for (int o = 8; o >= 1; o >>= 1)
                rs += __shfl_xor_sync(0xffffffffu, rs, o);
            float corr = __expf(m_i[i] - mnew);
            l_i[i] = l_i[i] * corr + rs;
            m_i[i] = mnew;
#pragma unroll
            for (int j = 0; j < 4; j++) acc[i][j] *= corr;
        }

        __syncthreads();   // all Kt reads done -> safe to overwrite with P
#pragma unroll
        for (int i = 0; i < 4; i++)
#pragma unroll
            for (int j = 0; j < 4; j++)
                Kt[(ty * 4 + i) * 65 + tx * 4 + j] = p[i][j];
        __syncthreads();

        // O += P @ V
#pragma unroll
        for (int kk = 0; kk < 64; kk++) {
            float a[4], bb[4];
#pragma unroll
            for (int i = 0; i < 4; i++) a[i] = Kt[(ty * 4 + i) * 65 + kk];
#pragma unroll
            for (int j = 0; j < 4; j++) bb[j] = Vs[kk * 64 + tx * 4 + j];
#pragma unroll
            for (int i = 0; i < 4; i++)
#pragma unroll
                for (int j = 0; j < 4; j++) acc[i][j] = fmaf(a[i], bb[j], acc[i][j]);
        }
        __syncthreads();   // before next tile overwrites Kt/Vs
    }

    // Normalize and write out[b, t, h*64 + d]
#pragma unroll
    for (int i = 0; i < 4; i++) {
        float inv = 1.0f / l_i[i];
        int t = qt * 64 + ty * 4 + i;
        float* op = out + ((size_t)b * T_ + t) * D_ + (size_t)h * HD_ + tx * 4;
#pragma unroll
        for (int j = 0; j < 4; j++) op[j] = acc[i][j] * inv;
    }
}

// ---------------------------------------------------------------------------
extern "C" void kernel_launch(void* const* d_in, const int* in_sizes, int n_in,
                              void* d_out, int out_size)
{
    const float* x  = (const float*)d_in[0];
    const float* Wq = (const float*)d_in[1];
    const float* Wk = (const float*)d_in[2];
    const float* Wv = (const float*)d_in[3];
    const float* wp = (const float*)d_in[4];
    float* out = (float*)d_out;

    // 49664 B dynamic smem (> 48K static limit) -> opt in. Idempotent, capture-safe.
    cudaFuncSetAttribute(palace_attn, cudaFuncAttributeMaxDynamicSharedMemorySize,
                         SMEM_BYTES);

    // QKV projections: N tiles=16, M tiles=128, z selects {q,k,v}
    qkv_gemm<<<dim3(16, 128, 3), 256>>>(x, Wq, Wk, Wv);

    // Attention: 32 q-tiles x 64 (b,h) pairs
    palace_attn<<<dim3(T_ / 64, B_ * H_), 256, SMEM_BYTES>>>(wp, out);
}

// round 3
// speedup vs baseline: 1.4595x; 1.4595x over previous
#include <cuda_runtime.h>
#include <math.h>

#define B_  4
#define T_  2048
#define D_  1024
#define H_  16
#define HD_ 64
#define BT_ (B_ * T_)

typedef unsigned long long u64;

__device__ float g_q[(size_t)BT_ * D_];
__device__ float g_k[(size_t)BT_ * D_];
__device__ float g_v[(size_t)BT_ * D_];

// ---- packed f32x2 helpers (FFMA2: 2 fp32 FMAs per instruction on sm_103a) ----
__device__ __forceinline__ u64 pk2(float lo, float hi) {
    u64 r; asm("mov.b64 %0,{%1,%2};" : "=l"(r) : "f"(lo), "f"(hi)); return r;
}
__device__ __forceinline__ void upk2(u64 v, float& lo, float& hi) {
    asm("mov.b64 {%0,%1},%2;" : "=f"(lo), "=f"(hi) : "l"(v));
}
__device__ __forceinline__ u64 fma2(u64 a, u64 b, u64 c) {
    u64 d; asm("fma.rn.f32x2 %0,%1,%2,%3;" : "=l"(d) : "l"(a), "l"(b), "l"(c)); return d;
}
__device__ __forceinline__ u64 mul2(u64 a, u64 b) {
    u64 d; asm("mul.rn.f32x2 %0,%1,%2;" : "=l"(d) : "l"(a), "l"(b)); return d;
}

// ---------------------------------------------------------------------------
// Kernel 1: y = x @ W^T. BM=BN=128, BK=16, 256 threads, 8x8 micro (4+4 split).
// A (x) tile row-major [128][17]: scalar broadcast a-loads, near-conflict-free
// stores. B (W) tile transposed [16][132]: conflict-free float4 b-loads.
// Inner loop: 32 FFMA2 per kk per thread.
// ---------------------------------------------------------------------------
__global__ __launch_bounds__(256, 2) void qkv_gemm(
    const float* __restrict__ x,
    const float* __restrict__ Wq,
    const float* __restrict__ Wk,
    const float* __restrict__ Wv)
{
    const float* W = (blockIdx.z == 0) ? Wq : ((blockIdx.z == 1) ? Wk : Wv);
    float* y = (blockIdx.z == 0) ? g_q : ((blockIdx.z == 1) ? g_k : g_v);

    __shared__ __align__(16) float As[128 * 17];
    __shared__ __align__(16) float Bs[16 * 132];

    const int tid = threadIdx.x;
    const int tx = tid & 15;
    const int ty = tid >> 4;
    const int m0 = blockIdx.y * 128;
    const int n0 = blockIdx.x * 128;

    const int lr  = tid >> 2;    // 0..63
    const int lc4 = tid & 3;     // 0..3 -> k-col group

    const float* xp = x + (size_t)(m0 + lr) * D_ + lc4 * 4;
    const float* wp = W + (size_t)(n0 + lr) * D_ + lc4 * 4;

    float4 a0 = *(const float4*)(xp);
    float4 a1 = *(const float4*)(xp + (size_t)64 * D_);
    float4 b0 = *(const float4*)(wp);
    float4 b1 = *(const float4*)(wp + (size_t)64 * D_);

    u64 acc[8][4];
#pragma unroll
    for (int i = 0; i < 8; i++)
#pragma unroll
        for (int j = 0; j < 4; j++) acc[i][j] = 0ull;

    for (int k0 = 0; k0 < D_; k0 += 16) {
        // commit prefetched tile to smem
        {
            float* ap = &As[lr * 17 + lc4 * 4];
            ap[0] = a0.x; ap[1] = a0.y; ap[2] = a0.z; ap[3] = a0.w;
            float* ap2 = &As[(lr + 64) * 17 + lc4 * 4];
            ap2[0] = a1.x; ap2[1] = a1.y; ap2[2] = a1.z; ap2[3] = a1.w;
            Bs[(lc4 * 4 + 0) * 132 + lr] = b0.x;
            Bs[(lc4 * 4 + 1) * 132 + lr] = b0.y;
            Bs[(lc4 * 4 + 2) * 132 + lr] = b0.z;
            Bs[(lc4 * 4 + 3) * 132 + lr] = b0.w;
            Bs[(lc4 * 4 + 0) * 132 + lr + 64] = b1.x;
            Bs[(lc4 * 4 + 1) * 132 + lr + 64] = b1.y;
            Bs[(lc4 * 4 + 2) * 132 + lr + 64] = b1.z;
            Bs[(lc4 * 4 + 3) * 132 + lr + 64] = b1.w;
        }
        __syncthreads();

        if (k0 + 16 < D_) {
            a0 = *(const float4*)(xp + k0 + 16);
            a1 = *(const float4*)(xp + (size_t)64 * D_ + k0 + 16);
            b0 = *(const float4*)(wp + k0 + 16);
            b1 = *(const float4*)(wp + (size_t)64 * D_ + k0 + 16);
        }

#pragma unroll 8
        for (int kk = 0; kk < 16; kk++) {
            float a[8];
#pragma unroll
            for (int i = 0; i < 4; i++) {
                a[i]     = As[(ty * 4 + i) * 17 + kk];
                a[4 + i] = As[(64 + ty * 4 + i) * 17 + kk];
            }
            ulonglong2 bb0 = *(const ulonglong2*)&Bs[kk * 132 + tx * 4];
            ulonglong2 bb1 = *(const ulonglong2*)&Bs[kk * 132 + 64 + tx * 4];
#pragma unroll
            for (int i = 0; i < 8; i++) {
                u64 av = pk2(a[i], a[i]);
                acc[i][0] = fma2(av, bb0.x, acc[i][0]);
                acc[i][1] = fma2(av, bb0.y, acc[i][1]);
                acc[i][2] = fma2(av, bb1.x, acc[i][2]);
                acc[i][3] = fma2(av, bb1.y, acc[i][3]);
            }
        }
        __syncthreads();
    }

#pragma unroll
    for (int i = 0; i < 8; i++) {
        int row = m0 + ((i < 4) ? (ty * 4 + i) : (64 + ty * 4 + i - 4));
        float4 o;
        upk2(acc[i][0], o.x, o.y); upk2(acc[i][1], o.z, o.w);
        *(float4*)&y[(size_t)row * D_ + n0 + tx * 4] = o;
        upk2(acc[i][2], o.x, o.y); upk2(acc[i][3], o.z, o.w);
        *(float4*)&y[(size_t)row * D_ + n0 + 64 + tx * 4] = o;
    }
}

// ---------------------------------------------------------------------------
// Kernel 2: palace-masked flash attention, 128q x 128k tiles, 256 threads,
// 8x8 micro on QK (4+4 split) and 8x4 on PV. All inner math in FFMA2.
// Smem: Qs[128][65] row-major, Kt[64][132] d-major, Vs[128][68] row-major,
// Ps[128][132] row-major. 169,472 B -> 1 CTA/SM.
// ---------------------------------------------------------------------------
#define SMEM_ATTN_BYTES ((128 * 65 + 64 * 132 + 128 * 68 + 128 * 132) * 4)

__global__ __launch_bounds__(256, 1) void palace_attn(
    const float* __restrict__ wp, float* __restrict__ out)
{
    extern __shared__ __align__(16) float sm[];
    float* Qs = sm;                              // 128*65  = 8320
    float* Kt = sm + 128 * 65;                   // 64*132  = 8448
    float* Vs = Kt + 64 * 132;                   // 128*68  = 8704
    float* Ps = Vs + 128 * 68;                   // 128*132 = 16896

    const int tid = threadIdx.x;
    const int tx = tid & 15;
    const int ty = tid >> 4;
    const int qt = blockIdx.x;
    const int bh = blockIdx.y;
    const int b = bh >> 4;
    const int h = bh & 15;

    const float sigw  = 1.0f / (1.0f + __expf(-wp[0]));
    const float scale = 0.125f;

    const size_t base = (size_t)b * T_ * D_ + (size_t)h * HD_;
    const float* qptr = g_q + base + (size_t)qt * 128 * D_;

    const int lc = tid >> 4;   // row loader 0..15
    const int d4 = tid & 15;   // col group 0..15

    // load Q tile [128][64] row-major
#pragma unroll
    for (int rr = lc; rr < 128; rr += 16) {
        float4 f = *(const float4*)(qptr + (size_t)rr * D_ + d4 * 4);
        float* qp = &Qs[rr * 65 + d4 * 4];
        qp[0] = f.x; qp[1] = f.y; qp[2] = f.z; qp[3] = f.w;
    }

    // per-row mask*scale: this thread's 8 key-cols all share block id tx>>1
    const int cb = tx >> 1;
    float mrow[8];
#pragma unroll
    for (int i = 0; i < 8; i++) {
        int r = (i < 4) ? (ty * 4 + i) : (64 + ty * 4 + i - 4);
        mrow[i] = (((r & 63) >> 3) == cb) ? scale : scale * sigw;
    }

    float m_i[8], l_i[8];
    u64 acc[8][2];
#pragma unroll
    for (int i = 0; i < 8; i++) {
        m_i[i] = -1e30f; l_i[i] = 0.0f;
        acc[i][0] = 0ull; acc[i][1] = 0ull;
    }

    __syncthreads();

    for (int kt = 0; kt < T_ / 128; kt++) {
        const float* kp = g_k + base + (size_t)kt * 128 * D_;
        const float* vp = g_v + base + (size_t)kt * 128 * D_;
#pragma unroll
        for (int rr = lc; rr < 128; rr += 16) {
            float4 kf = *(const float4*)(kp + (size_t)rr * D_ + d4 * 4);
            Kt[(d4 * 4 + 0) * 132 + rr] = kf.x;
            Kt[(d4 * 4 + 1) * 132 + rr] = kf.y;
            Kt[(d4 * 4 + 2) * 132 + rr] = kf.z;
            Kt[(d4 * 4 + 3) * 132 + rr] = kf.w;
            float4 vf = *(const float4*)(vp + (size_t)rr * D_ + d4 * 4);
            *(float4*)&Vs[rr * 68 + d4 * 4] = vf;
        }
        __syncthreads();

        // S = Q @ K^T : 8 rows x 8 cols per thread, packed pairs
        u64 s2[8][4];
#pragma unroll
        for (int i = 0; i < 8; i++)
#pragma unroll
            for (int j = 0; j < 4; j++) s2[i][j] = 0ull;

#pragma unroll 4
        for (int d = 0; d < 64; d++) {
            ulonglong2 k0v = *(const ulonglong2*)&Kt[d * 132 + tx * 4];
            ulonglong2 k1v = *(const ulonglong2*)&Kt[d * 132 + 64 + tx * 4];
#pragma unroll
            for (int i = 0; i < 8; i++) {
                int r = (i < 4) ? (ty * 4 + i) : (64 + ty * 4 + i - 4);
                u64 av = pk2(Qs[r * 65 + d], Qs[r * 65 + d]);
                s2[i][0] = fma2(av, k0v.x, s2[i][0]);
                s2[i][1] = fma2(av, k0v.y, s2[i][1]);
                s2[i][2] = fma2(av, k1v.x, s2[i][2]);
                s2[i][3] = fma2(av, k1v.y, s2[i][3]);
            }
        }

        // online softmax, row by row; write P to smem
#pragma unroll
        for (int i = 0; i < 8; i++) {
            int r = (i < 4) ? (ty * 4 + i) : (64 + ty * 4 + i - 4);
            float s[8];
            upk2(s2[i][0], s[0], s[1]); upk2(s2[i][1], s[2], s[3]);
            upk2(s2[i][2], s[4], s[5]); upk2(s2[i][3], s[6], s[7]);
            float mr = mrow[i];
#pragma unroll
            for (int j = 0; j < 8; j++) s[j] *= mr;
            float mx = s[0];
#pragma unroll
            for (int j = 1; j < 8; j++) mx = fmaxf(mx, s[j]);
#pragma unroll
            for (int o = 8; o >= 1; o >>= 1)
                mx = fmaxf(mx, __shfl_xor_sync(0xffffffffu, mx, o));
            float mn = fmaxf(m_i[i], mx);
            float p[8], rs = 0.0f;
#pragma unroll
            for (int j = 0; j < 8; j++) { p[j] = __expf(s[j] - mn); rs += p[j]; }
#pragma unroll
            for (int o = 8; o >= 1; o >>= 1)
                rs += __shfl_xor_sync(0xffffffffu, rs, o);
            float corr = __expf(m_i[i] - mn);
            l_i[i] = l_i[i] * corr + rs;
            m_i[i] = mn;
            u64 c2 = pk2(corr, corr);
            acc[i][0] = mul2(acc[i][0], c2);
            acc[i][1] = mul2(acc[i][1], c2);
            *(float4*)&Ps[r * 132 + tx * 4]      = make_float4(p[0], p[1], p[2], p[3]);
            *(float4*)&Ps[r * 132 + 64 + tx * 4] = make_float4(p[4], p[5], p[6], p[7]);
        }
        __syncthreads();

        // O += P @ V : 8 rows x 4 d-cols per thread
#pragma unroll 4
        for (int kk = 0; kk < 128; kk++) {
            ulonglong2 vv = *(const ulonglong2*)&Vs[kk * 68 + tx * 4];
#pragma unroll
            for (int i = 0; i < 8; i++) {
                int r = (i < 4) ? (ty * 4 + i) : (64 + ty * 4 + i - 4);
                u64 av = pk2(Ps[r * 132 + kk], Ps[r * 132 + kk]);
                acc[i][0] = fma2(av, vv.x, acc[i][0]);
                acc[i][1] = fma2(av, vv.y, acc[i][1]);
            }
        }
        __syncthreads();
    }

#pragma unroll
    for (int i = 0; i < 8; i++) {
        int r = (i < 4) ? (ty * 4 + i) : (64 + ty * 4 + i - 4);
        float inv = 1.0f / l_i[i];
        float4 o;
        upk2(acc[i][0], o.x, o.y); upk2(acc[i][1], o.z, o.w);
        o.x *= inv; o.y *= inv; o.z *= inv; o.w *= inv;
        int t = qt * 128 + r;
        *(float4*)&out[((size_t)b * T_ + t) * D_ + (size_t)h * HD_ + tx * 4] = o;
    }
}

// ---------------------------------------------------------------------------
extern "C" void kernel_launch(void* const* d_in, const int* in_sizes, int n_in,
                              void* d_out, int out_size)
{
    const float* x  = (const float*)d_in[0];
    const float* Wq = (const float*)d_in[1];
    const float* Wk = (const float*)d_in[2];
    const float* Wv = (const float*)d_in[3];
    const float* wp = (const float*)d_in[4];
    float* out = (float*)d_out;

    cudaFuncSetAttribute(palace_attn, cudaFuncAttributeMaxDynamicSharedMemorySize,
                         SMEM_ATTN_BYTES);

    qkv_gemm<<<dim3(8, 64, 3), 256>>>(x, Wq, Wk, Wv);
    palace_attn<<<dim3(T_ / 128, B_ * H_), 256, SMEM_ATTN_BYTES>>>(wp, out);
}

// round 5
// speedup vs baseline: 1.8508x; 1.2681x over previous
#include <cuda_runtime.h>
#include <cuda_bf16.h>
#include <cstdint>
#include <math.h>

#define B_  4
#define T_  2048
#define D_  1024
#define H_  16
#define HD_ 64
#define BT_ (B_ * T_)

typedef unsigned long long u64;

__device__ float g_q[(size_t)BT_ * D_];
__device__ float g_k[(size_t)BT_ * D_];
__device__ float g_v[(size_t)BT_ * D_];
__device__ __nv_bfloat16 g_xh[(size_t)BT_ * D_];
__device__ __nv_bfloat16 g_xl[(size_t)BT_ * D_];
__device__ __nv_bfloat16 g_wh[3ull * D_ * D_];
__device__ __nv_bfloat16 g_wl[3ull * D_ * D_];

// ---- portable PTX helpers (sm_80+ only; NO tcgen05 — ptxas targets sm_103) --
__device__ __forceinline__ uint32_t smem_u32(const void* p) {
    uint32_t a;
    asm("{ .reg .u64 t; cvta.to.shared.u64 t, %1; cvt.u32.u64 %0, t; }"
        : "=r"(a) : "l"(p));
    return a;
}
__device__ __forceinline__ void cp16(uint32_t s, const void* g) {
    asm volatile("cp.async.cg.shared.global [%0], [%1], 16;"
                 :: "r"(s), "l"(g) : "memory");
}
#define CP_COMMIT() asm volatile("cp.async.commit_group;" ::: "memory")
#define CP_WAIT(n)  asm volatile("cp.async.wait_group %0;" :: "n"(n) : "memory")

__device__ __forceinline__ void mma_bf16(float& d0, float& d1, float& d2, float& d3,
                                         uint32_t a0, uint32_t a1, uint32_t a2, uint32_t a3,
                                         uint32_t b0, uint32_t b1) {
    asm volatile("mma.sync.aligned.m16n8k16.row.col.f32.bf16.bf16.f32 "
                 "{%0,%1,%2,%3},{%4,%5,%6,%7},{%8,%9},{%0,%1,%2,%3};"
                 : "+f"(d0), "+f"(d1), "+f"(d2), "+f"(d3)
                 : "r"(a0), "r"(a1), "r"(a2), "r"(a3), "r"(b0), "r"(b1));
}

// ---- packed f32x2 helpers -------------------------------------------------
__device__ __forceinline__ u64 pk2(float lo, float hi) {
    u64 r; asm("mov.b64 %0,{%1,%2};" : "=l"(r) : "f"(lo), "f"(hi)); return r;
}
__device__ __forceinline__ void upk2(u64 v, float& lo, float& hi) {
    asm("mov.b64 {%0,%1},%2;" : "=f"(lo), "=f"(hi) : "l"(v));
}
__device__ __forceinline__ u64 fma2(u64 a, u64 b, u64 c) {
    u64 d; asm("fma.rn.f32x2 %0,%1,%2,%3;" : "=l"(d) : "l"(a), "l"(b), "l"(c)); return d;
}
__device__ __forceinline__ u64 mul2(u64 a, u64 b) {
    u64 d; asm("mul.rn.f32x2 %0,%1,%2;" : "=l"(d) : "l"(a), "l"(b)); return d;
}

// ===========================================================================
// Kernel 0: fp32 -> bf16 hi/lo split
// ===========================================================================
__global__ __launch_bounds__(256) void convert_split(
    const float* __restrict__ src, __nv_bfloat16* __restrict__ hi,
    __nv_bfloat16* __restrict__ lo, int n4)
{
    int i = blockIdx.x * blockDim.x + threadIdx.x;
    if (i >= n4) return;
    float4 v = ((const float4*)src)[i];
    float vv[4] = {v.x, v.y, v.z, v.w};
    uint2 hp, lp;
    unsigned short* hu = (unsigned short*)&hp;
    unsigned short* lu = (unsigned short*)&lp;
#pragma unroll
    for (int j = 0; j < 4; j++) {
        __nv_bfloat16 h = __float2bfloat16(vv[j]);
        float hf = __bfloat162float(h);
        __nv_bfloat16 l = __float2bfloat16(vv[j] - hf);
        hu[j] = __bfloat16_as_ushort(h);
        lu[j] = __bfloat16_as_ushort(l);
    }
    ((uint2*)hi)[i] = hp;
    ((uint2*)lo)[i] = lp;
}

// ===========================================================================
// Kernel 1: QKV projection via mma.sync bf16 (hi/lo split, fp32 accum).
// Grid (8 n-tiles, 64 m-tiles, 3 mats), 256 threads.
// Block tile 128x128, BK=32. Warps 4x2; warp tile 32x64 = 2x8 m16n8k16.
// Smem: per buffer 4 tiles (A_hi, A_lo, B_hi, B_lo), each 128 rows x 32 bf16
// padded to 40 (stride 20 words -> conflict-free frag loads). Double buffered
// with cp.async.cg.
// ===========================================================================
#define TILE_E   (128 * 40)          // bf16 elements per tile
#define TILE_B   (TILE_E * 2)        // 10240 bytes
#define GEMM_SMEM (2 * 4 * TILE_B)   // 81920 bytes

__global__ __launch_bounds__(256, 2) void qkv_gemm_mma()
{
    extern __shared__ __align__(16) char smem[];
    __nv_bfloat16* sb = (__nv_bfloat16*)smem;
    const uint32_t sbase = smem_u32(smem);

    const int tid  = threadIdx.x;
    const int lane = tid & 31;
    const int wid  = tid >> 5;
    const int wm   = (wid >> 1) * 32;   // warp m offset (0,32,64,96)
    const int wn   = (wid & 1) * 64;    // warp n offset (0,64)
    const int n0   = blockIdx.x * 128;
    const int m0   = blockIdx.y * 128;
    const int mat  = blockIdx.z;

    const __nv_bfloat16* Ah_g = g_xh + (size_t)m0 * D_;
    const __nv_bfloat16* Al_g = g_xl + (size_t)m0 * D_;
    const __nv_bfloat16* Bh_g = g_wh + (size_t)mat * D_ * D_ + (size_t)n0 * D_;
    const __nv_bfloat16* Bl_g = g_wl + (size_t)mat * D_ * D_ + (size_t)n0 * D_;
    float* y = (mat == 0) ? g_q : ((mat == 1) ? g_k : g_v);

    const int lrow  = tid >> 1;         // 0..127
    const int lhalf = tid & 1;          // 16-bf16 half of the 32-col row

    float acc[2][8][4];
#pragma unroll
    for (int i = 0; i < 2; i++)
#pragma unroll
        for (int j = 0; j < 8; j++)
#pragma unroll
            for (int c = 0; c < 4; c++) acc[i][j][c] = 0.0f;

    const int r  = lane >> 2;           // 0..7
    const int c2 = (lane & 3) * 2;      // 0,2,4,6

    auto load_tiles = [&](int buf, int k0) {
        const size_t go = (size_t)lrow * D_ + k0 + lhalf * 16;
        const uint32_t so = sbase + buf * 4 * TILE_B + lrow * 80 + lhalf * 32;
        cp16(so + 0 * TILE_B,      Ah_g + go);
        cp16(so + 0 * TILE_B + 16, Ah_g + go + 8);
        cp16(so + 1 * TILE_B,      Al_g + go);
        cp16(so + 1 * TILE_B + 16, Al_g + go + 8);
        cp16(so + 2 * TILE_B,      Bh_g + go);
        cp16(so + 2 * TILE_B + 16, Bh_g + go + 8);
        cp16(so + 3 * TILE_B,      Bl_g + go);
        cp16(so + 3 * TILE_B + 16, Bl_g + go + 8);
    };

    load_tiles(0, 0);
    CP_COMMIT();

    for (int it = 0; it < 32; it++) {
        const int cur = it & 1;
        if (it + 1 < 32) {
            load_tiles(cur ^ 1, (it + 1) * 32);
            CP_COMMIT();
            CP_WAIT(1);
        } else {
            CP_WAIT(0);
        }
        __syncthreads();

        const __nv_bfloat16* Ah = sb + (cur * 4 + 0) * TILE_E;
        const __nv_bfloat16* Al = sb + (cur * 4 + 1) * TILE_E;
        const __nv_bfloat16* Bh = sb + (cur * 4 + 2) * TILE_E;
        const __nv_bfloat16* Bl = sb + (cur * 4 + 3) * TILE_E;

#pragma unroll
        for (int ks = 0; ks < 2; ks++) {
            const int kof = ks * 16;
            uint32_t ah[2][4], al[2][4];
#pragma unroll
            for (int mm = 0; mm < 2; mm++) {
                int row0 = wm + mm * 16 + r;
                const __nv_bfloat16* p = Ah + row0 * 40 + kof + c2;
                ah[mm][0] = *(const uint32_t*)(p);
                ah[mm][1] = *(const uint32_t*)(p + 8 * 40);
                ah[mm][2] = *(const uint32_t*)(p + 8);
                ah[mm][3] = *(const uint32_t*)(p + 8 * 40 + 8);
                const __nv_bfloat16* q = Al + row0 * 40 + kof + c2;
                al[mm][0] = *(const uint32_t*)(q);
                al[mm][1] = *(const uint32_t*)(q + 8 * 40);
                al[mm][2] = *(const uint32_t*)(q + 8);
                al[mm][3] = *(const uint32_t*)(q + 8 * 40 + 8);
            }
#pragma unroll
            for (int nn = 0; nn < 8; nn++) {
                int nrow = wn + nn * 8 + r;
                const __nv_bfloat16* pb = Bh + nrow * 40 + kof + c2;
                uint32_t bh0 = *(const uint32_t*)(pb);
                uint32_t bh1 = *(const uint32_t*)(pb + 8);
                const __nv_bfloat16* qb = Bl + nrow * 40 + kof + c2;
                uint32_t bl0 = *(const uint32_t*)(qb);
                uint32_t bl1 = *(const uint32_t*)(qb + 8);
#pragma unroll
                for (int mm = 0; mm < 2; mm++) {
                    float* d = acc[mm][nn];
                    mma_bf16(d[0], d[1], d[2], d[3],
                             ah[mm][0], ah[mm][1], ah[mm][2], ah[mm][3], bh0, bh1);
                    mma_bf16(d[0], d[1], d[2], d[3],
                             ah[mm][0], ah[mm][1], ah[mm][2], ah[mm][3], bl0, bl1);
                    mma_bf16(d[0], d[1], d[2], d[3],
                             al[mm][0], al[mm][1], al[mm][2], al[mm][3], bh0, bh1);
                }
            }
        }
        __syncthreads();
    }

    // write out D fragments: rows m0+wm+mm*16+{r,r+8}, cols n0+wn+nn*8+c2(+1)
#pragma unroll
    for (int mm = 0; mm < 2; mm++) {
#pragma unroll
        for (int nn = 0; nn < 8; nn++) {
            int row = m0 + wm + mm * 16 + r;
            int col = n0 + wn + nn * 8 + c2;
            float2 v0 = make_float2(acc[mm][nn][0], acc[mm][nn][1]);
            float2 v1 = make_float2(acc[mm][nn][2], acc[mm][nn][3]);
            *(float2*)&y[(size_t)row * D_ + col] = v0;
            *(float2*)&y[(size_t)(row + 8) * D_ + col] = v1;
        }
    }
}

// ===========================================================================
// Kernel 2: palace-masked flash attention (FFMA2 path, unchanged — passing)
// ===========================================================================
#define SMEM_ATTN_BYTES ((128 * 65 + 64 * 132 + 128 * 68 + 128 * 132) * 4)

__global__ __launch_bounds__(256, 1) void palace_attn(
    const float* __restrict__ wp, float* __restrict__ out)
{
    extern __shared__ __align__(16) float sm[];
    float* Qs = sm;
    float* Kt = sm + 128 * 65;
    float* Vs = Kt + 64 * 132;
    float* Ps = Vs + 128 * 68;

    const int tid = threadIdx.x;
    const int tx = tid & 15;
    const int ty = tid >> 4;
    const int qt = blockIdx.x;
    const int bh = blockIdx.y;
    const int b = bh >> 4;
    const int h = bh & 15;

    const float sigw  = 1.0f / (1.0f + __expf(-wp[0]));
    const float scale = 0.125f;

    const size_t base = (size_t)b * T_ * D_ + (size_t)h * HD_;
    const float* qptr = g_q + base + (size_t)qt * 128 * D_;

    const int lc = tid >> 4;
    const int d4 = tid & 15;

#pragma unroll
    for (int rr = lc; rr < 128; rr += 16) {
        float4 f = *(const float4*)(qptr + (size_t)rr * D_ + d4 * 4);
        float* qp = &Qs[rr * 65 + d4 * 4];
        qp[0] = f.x; qp[1] = f.y; qp[2] = f.z; qp[3] = f.w;
    }

    const int cb = tx >> 1;
    float mrow[8];
#pragma unroll
    for (int i = 0; i < 8; i++) {
        int r = (i < 4) ? (ty * 4 + i) : (64 + ty * 4 + i - 4);
        mrow[i] = (((r & 63) >> 3) == cb) ? scale : scale * sigw;
    }

    float m_i[8], l_i[8];
    u64 acc[8][2];
#pragma unroll
    for (int i = 0; i < 8; i++) {
        m_i[i] = -1e30f; l_i[i] = 0.0f;
        acc[i][0] = 0ull; acc[i][1] = 0ull;
    }

    __syncthreads();

    for (int kt = 0; kt < T_ / 128; kt++) {
        const float* kp = g_k + base + (size_t)kt * 128 * D_;
        const float* vp = g_v + base + (size_t)kt * 128 * D_;
#pragma unroll
        for (int rr = lc; rr < 128; rr += 16) {
            float4 kf = *(const float4*)(kp + (size_t)rr * D_ + d4 * 4);
            Kt[(d4 * 4 + 0) * 132 + rr] = kf.x;
            Kt[(d4 * 4 + 1) * 132 + rr] = kf.y;
            Kt[(d4 * 4 + 2) * 132 + rr] = kf.z;
            Kt[(d4 * 4 + 3) * 132 + rr] = kf.w;
            float4 vf = *(const float4*)(vp + (size_t)rr * D_ + d4 * 4);
            *(float4*)&Vs[rr * 68 + d4 * 4] = vf;
        }
        __syncthreads();

        u64 s2[8][4];
#pragma unroll
        for (int i = 0; i < 8; i++)
#pragma unroll
            for (int j = 0; j < 4; j++) s2[i][j] = 0ull;

#pragma unroll 4
        for (int d = 0; d < 64; d++) {
            ulonglong2 k0v = *(const ulonglong2*)&Kt[d * 132 + tx * 4];
            ulonglong2 k1v = *(const ulonglong2*)&Kt[d * 132 + 64 + tx * 4];
#pragma unroll
            for (int i = 0; i < 8; i++) {
                int r = (i < 4) ? (ty * 4 + i) : (64 + ty * 4 + i - 4);
                u64 av = pk2(Qs[r * 65 + d], Qs[r * 65 + d]);
                s2[i][0] = fma2(av, k0v.x, s2[i][0]);
                s2[i][1] = fma2(av, k0v.y, s2[i][1]);
                s2[i][2] = fma2(av, k1v.x, s2[i][2]);
                s2[i][3] = fma2(av, k1v.y, s2[i][3]);
            }
        }

#pragma unroll
        for (int i = 0; i < 8; i++) {
            int r = (i < 4) ? (ty * 4 + i) : (64 + ty * 4 + i - 4);
            float s[8];
            upk2(s2[i][0], s[0], s[1]); upk2(s2[i][1], s[2], s[3]);
            upk2(s2[i][2], s[4], s[5]); upk2(s2[i][3], s[6], s[7]);
            float mr = mrow[i];
#pragma unroll
            for (int j = 0; j < 8; j++) s[j] *= mr;
            float mx = s[0];
#pragma unroll
            for (int j = 1; j < 8; j++) mx = fmaxf(mx, s[j]);
#pragma unroll
            for (int o = 8; o >= 1; o >>= 1)
                mx = fmaxf(mx, __shfl_xor_sync(0xffffffffu, mx, o));
            float mn = fmaxf(m_i[i], mx);
            float p[8], rs = 0.0f;
#pragma unroll
            for (int j = 0; j < 8; j++) { p[j] = __expf(s[j] - mn); rs += p[j]; }
#pragma unroll
            for (int o = 8; o >= 1; o >>= 1)
                rs += __shfl_xor_sync(0xffffffffu, rs, o);
            float corr = __expf(m_i[i] - mn);
            l_i[i] = l_i[i] * corr + rs;
            m_i[i] = mn;
            u64 c2 = pk2(corr, corr);
            acc[i][0] = mul2(acc[i][0], c2);
            acc[i][1] = mul2(acc[i][1], c2);
            *(float4*)&Ps[r * 132 + tx * 4]      = make_float4(p[0], p[1], p[2], p[3]);
            *(float4*)&Ps[r * 132 + 64 + tx * 4] = make_float4(p[4], p[5], p[6], p[7]);
        }
        __syncthreads();

#pragma unroll 4
        for (int kk = 0; kk < 128; kk++) {
            ulonglong2 vv = *(const ulonglong2*)&Vs[kk * 68 + tx * 4];
#pragma unroll
            for (int i = 0; i < 8; i++) {
                int r = (i < 4) ? (ty * 4 + i) : (64 + ty * 4 + i - 4);
                u64 av = pk2(Ps[r * 132 + kk], Ps[r * 132 + kk]);
                acc[i][0] = fma2(av, vv.x, acc[i][0]);
                acc[i][1] = fma2(av, vv.y, acc[i][1]);
            }
        }
        __syncthreads();
    }

#pragma unroll
    for (int i = 0; i < 8; i++) {
        int r = (i < 4) ? (ty * 4 + i) : (64 + ty * 4 + i - 4);
        float inv = 1.0f / l_i[i];
        float4 o;
        upk2(acc[i][0], o.x, o.y); upk2(acc[i][1], o.z, o.w);
        o.x *= inv; o.y *= inv; o.z *= inv; o.w *= inv;
        int t = qt * 128 + r;
        *(float4*)&out[((size_t)b * T_ + t) * D_ + (size_t)h * HD_ + tx * 4] = o;
    }
}

// ---------------------------------------------------------------------------
extern "C" void kernel_launch(void* const* d_in, const int* in_sizes, int n_in,
                              void* d_out, int out_size)
{
    const float* x  = (const float*)d_in[0];
    const float* Wq = (const float*)d_in[1];
    const float* Wk = (const float*)d_in[2];
    const float* Wv = (const float*)d_in[3];
    const float* wp = (const float*)d_in[4];
    float* out = (float*)d_out;

    __nv_bfloat16 *xh, *xl, *wh, *wl;
    cudaGetSymbolAddress((void**)&xh, g_xh);
    cudaGetSymbolAddress((void**)&xl, g_xl);
    cudaGetSymbolAddress((void**)&wh, g_wh);
    cudaGetSymbolAddress((void**)&wl, g_wl);

    cudaFuncSetAttribute(qkv_gemm_mma, cudaFuncAttributeMaxDynamicSharedMemorySize,
                         GEMM_SMEM);
    cudaFuncSetAttribute(palace_attn, cudaFuncAttributeMaxDynamicSharedMemorySize,
                         SMEM_ATTN_BYTES);

    int n4x = BT_ * D_ / 4;
    convert_split<<<(n4x + 255) / 256, 256>>>(x, xh, xl, n4x);
    int n4w = D_ * D_ / 4;
    convert_split<<<(n4w + 255) / 256, 256>>>(Wq, wh,                   wl,                   n4w);
    convert_split<<<(n4w + 255) / 256, 256>>>(Wk, wh + (size_t)D_ * D_, wl + (size_t)D_ * D_, n4w);
    convert_split<<<(n4w + 255) / 256, 256>>>(Wv, wh + 2ull * D_ * D_,  wl + 2ull * D_ * D_,  n4w);

    qkv_gemm_mma<<<dim3(8, 64, 3), 256, GEMM_SMEM>>>();
    palace_attn<<<dim3(T_ / 128, B_ * H_), 256, SMEM_ATTN_BYTES>>>(wp, out);
}

// round 6
// speedup vs baseline: 3.1776x; 1.7169x over previous
#include <cuda_runtime.h>
#include <cuda_bf16.h>
#include <cstdint>
#include <math.h>

#define B_  4
#define T_  2048
#define D_  1024
#define H_  16
#define BT_ (B_ * T_)
#define LOG2E 1.4426950408889634f

// bf16 hi/lo storage for all operands (split arithmetic on tensor cores)
__device__ __nv_bfloat16 g_xh[(size_t)BT_ * D_];
__device__ __nv_bfloat16 g_xl[(size_t)BT_ * D_];
__device__ __nv_bfloat16 g_wh[3ull * D_ * D_];
__device__ __nv_bfloat16 g_wl[3ull * D_ * D_];
__device__ __nv_bfloat16 g_qh[(size_t)BT_ * D_];
__device__ __nv_bfloat16 g_ql[(size_t)BT_ * D_];
__device__ __nv_bfloat16 g_kh[(size_t)BT_ * D_];
__device__ __nv_bfloat16 g_kl[(size_t)BT_ * D_];
__device__ __nv_bfloat16 g_vh[(size_t)BT_ * D_];
__device__ __nv_bfloat16 g_vl[(size_t)BT_ * D_];

// ---- portable PTX helpers (sm_80-era only; ptxas target is sm_103) --------
__device__ __forceinline__ uint32_t smem_u32(const void* p) {
    uint32_t a;
    asm("{ .reg .u64 t; cvta.to.shared.u64 t, %1; cvt.u32.u64 %0, t; }"
        : "=r"(a) : "l"(p));
    return a;
}
__device__ __forceinline__ void cp16(uint32_t s, const void* g) {
    asm volatile("cp.async.cg.shared.global [%0], [%1], 16;"
                 :: "r"(s), "l"(g) : "memory");
}
#define CP_COMMIT() asm volatile("cp.async.commit_group;" ::: "memory")
#define CP_WAIT(n)  asm volatile("cp.async.wait_group %0;" :: "n"(n) : "memory")

__device__ __forceinline__ void mma_bf16(float& d0, float& d1, float& d2, float& d3,
                                         uint32_t a0, uint32_t a1, uint32_t a2, uint32_t a3,
                                         uint32_t b0, uint32_t b1) {
    asm volatile("mma.sync.aligned.m16n8k16.row.col.f32.bf16.bf16.f32 "
                 "{%0,%1,%2,%3},{%4,%5,%6,%7},{%8,%9},{%0,%1,%2,%3};"
                 : "+f"(d0), "+f"(d1), "+f"(d2), "+f"(d3)
                 : "r"(a0), "r"(a1), "r"(a2), "r"(a3), "r"(b0), "r"(b1));
}
__device__ __forceinline__ void ldsm4t(uint32_t& r0, uint32_t& r1,
                                       uint32_t& r2, uint32_t& r3, uint32_t a) {
    asm volatile("ldmatrix.sync.aligned.m8n8.x4.trans.shared.b16 {%0,%1,%2,%3}, [%4];"
                 : "=r"(r0), "=r"(r1), "=r"(r2), "=r"(r3) : "r"(a));
}
// pack two f32 into bf16x2 (lo at low half)
__device__ __forceinline__ uint32_t packbf(float lo, float hi) {
    __nv_bfloat162 t = __floats2bfloat162_rn(lo, hi);
    return *(uint32_t*)&t;
}
// exp2 via FMA-pipe polynomial (no MUFU): |err| ~1e-7 on f in [-.5,.5]
__device__ __forceinline__ float exp2p(float x) {
    x = fmaxf(x, -80.0f);
    float t = x + 12582912.0f;            // round-to-nearest int (RN magic)
    float n = t - 12582912.0f;
    float f = x - n;
    float p =             1.5403530e-4f;
    p = fmaf(p, f, 1.3333558e-3f);
    p = fmaf(p, f, 9.6181291e-3f);
    p = fmaf(p, f, 5.5504109e-2f);
    p = fmaf(p, f, 2.4022651e-1f);
    p = fmaf(p, f, 6.9314718e-1f);
    p = fmaf(p, f, 1.0f);
    int e = __float_as_int(t) - 0x4B400000;       // = (int)n
    float sc = __int_as_float((e + 127) << 23);   // 2^n
    return p * sc;
}

// ===========================================================================
// Kernel 0: fp32 -> bf16 hi/lo split
// ===========================================================================
__global__ __launch_bounds__(256) void convert_split(
    const float* __restrict__ src, __nv_bfloat16* __restrict__ hi,
    __nv_bfloat16* __restrict__ lo, int n4)
{
    int i = blockIdx.x * blockDim.x + threadIdx.x;
    if (i >= n4) return;
    float4 v = ((const float4*)src)[i];
    float vv[4] = {v.x, v.y, v.z, v.w};
    uint2 hp, lp;
    unsigned short* hu = (unsigned short*)&hp;
    unsigned short* lu = (unsigned short*)&lp;
#pragma unroll
    for (int j = 0; j < 4; j++) {
        __nv_bfloat16 h = __float2bfloat16(vv[j]);
        float hf = __bfloat162float(h);
        __nv_bfloat16 l = __float2bfloat16(vv[j] - hf);
        hu[j] = __bfloat16_as_ushort(h);
        lu[j] = __bfloat16_as_ushort(l);
    }
    ((uint2*)hi)[i] = hp;
    ((uint2*)lo)[i] = lp;
}

// ===========================================================================
// Kernel 1: QKV projection via mma.sync bf16 (hi/lo split, fp32 accum).
// Same mainloop as R5; epilogue now writes bf16 hi/lo pairs for attention.
// ===========================================================================
#define TILE_E   (128 * 40)
#define TILE_B   (TILE_E * 2)
#define GEMM_SMEM (2 * 4 * TILE_B)

__global__ __launch_bounds__(256, 2) void qkv_gemm_mma()
{
    extern __shared__ __align__(16) char smem[];
    __nv_bfloat16* sb = (__nv_bfloat16*)smem;
    const uint32_t sbase = smem_u32(smem);

    const int tid  = threadIdx.x;
    const int lane = tid & 31;
    const int wid  = tid >> 5;
    const int wm   = (wid >> 1) * 32;
    const int wn   = (wid & 1) * 64;
    const int n0   = blockIdx.x * 128;
    const int m0   = blockIdx.y * 128;
    const int mat  = blockIdx.z;

    const __nv_bfloat16* Ah_g = g_xh + (size_t)m0 * D_;
    const __nv_bfloat16* Al_g = g_xl + (size_t)m0 * D_;
    const __nv_bfloat16* Bh_g = g_wh + (size_t)mat * D_ * D_ + (size_t)n0 * D_;
    const __nv_bfloat16* Bl_g = g_wl + (size_t)mat * D_ * D_ + (size_t)n0 * D_;
    __nv_bfloat16 *yh, *yl;
    if (mat == 0)      { yh = g_qh; yl = g_ql; }
    else if (mat == 1) { yh = g_kh; yl = g_kl; }
    else               { yh = g_vh; yl = g_vl; }

    const int lrow  = tid >> 1;
    const int lhalf = tid & 1;

    float acc[2][8][4];
#pragma unroll
    for (int i = 0; i < 2; i++)
#pragma unroll
        for (int j = 0; j < 8; j++)
#pragma unroll
            for (int c = 0; c < 4; c++) acc[i][j][c] = 0.0f;

    const int r  = lane >> 2;
    const int c2 = (lane & 3) * 2;

    auto load_tiles = [&](int buf, int k0) {
        const size_t go = (size_t)lrow * D_ + k0 + lhalf * 16;
        const uint32_t so = sbase + buf * 4 * TILE_B + lrow * 80 + lhalf * 32;
        cp16(so + 0 * TILE_B,      Ah_g + go);
        cp16(so + 0 * TILE_B + 16, Ah_g + go + 8);
        cp16(so + 1 * TILE_B,      Al_g + go);
        cp16(so + 1 * TILE_B + 16, Al_g + go + 8);
        cp16(so + 2 * TILE_B,      Bh_g + go);
        cp16(so + 2 * TILE_B + 16, Bh_g + go + 8);
        cp16(so + 3 * TILE_B,      Bl_g + go);
        cp16(so + 3 * TILE_B + 16, Bl_g + go + 8);
    };

    load_tiles(0, 0);
    CP_COMMIT();

    for (int it = 0; it < 32; it++) {
        const int cur = it & 1;
        if (it + 1 < 32) {
            load_tiles(cur ^ 1, (it + 1) * 32);
            CP_COMMIT();
            CP_WAIT(1);
        } else {
            CP_WAIT(0);
        }
        __syncthreads();

        const __nv_bfloat16* Ah = sb + (cur * 4 + 0) * TILE_E;
        const __nv_bfloat16* Al = sb + (cur * 4 + 1) * TILE_E;
        const __nv_bfloat16* Bh = sb + (cur * 4 + 2) * TILE_E;
        const __nv_bfloat16* Bl = sb + (cur * 4 + 3) * TILE_E;

#pragma unroll
        for (int ks = 0; ks < 2; ks++) {
            const int kof = ks * 16;
            uint32_t ah[2][4], al[2][4];
#pragma unroll
            for (int mm = 0; mm < 2; mm++) {
                int row0 = wm + mm * 16 + r;
                const __nv_bfloat16* p = Ah + row0 * 40 + kof + c2;
                ah[mm][0] = *(const uint32_t*)(p);
                ah[mm][1] = *(const uint32_t*)(p + 8 * 40);
                ah[mm][2] = *(const uint32_t*)(p + 8);
                ah[mm][3] = *(const uint32_t*)(p + 8 * 40 + 8);
                const __nv_bfloat16* q = Al + row0 * 40 + kof + c2;
                al[mm][0] = *(const uint32_t*)(q);
                al[mm][1] = *(const uint32_t*)(q + 8 * 40);
                al[mm][2] = *(const uint32_t*)(q + 8);
                al[mm][3] = *(const uint32_t*)(q + 8 * 40 + 8);
            }
#pragma unroll
            for (int nn = 0; nn < 8; nn++) {
                int nrow = wn + nn * 8 + r;
                const __nv_bfloat16* pb = Bh + nrow * 40 + kof + c2;
                uint32_t bh0 = *(const uint32_t*)(pb);
                uint32_t bh1 = *(const uint32_t*)(pb + 8);
                const __nv_bfloat16* qb = Bl + nrow * 40 + kof + c2;
                uint32_t bl0 = *(const uint32_t*)(qb);
                uint32_t bl1 = *(const uint32_t*)(qb + 8);
#pragma unroll
                for (int mm = 0; mm < 2; mm++) {
                    float* d = acc[mm][nn];
                    mma_bf16(d[0], d[1], d[2], d[3],
                             ah[mm][0], ah[mm][1], ah[mm][2], ah[mm][3], bh0, bh1);
                    mma_bf16(d[0], d[1], d[2], d[3],
                             ah[mm][0], ah[mm][1], ah[mm][2], ah[mm][3], bl0, bl1);
                    mma_bf16(d[0], d[1], d[2], d[3],
                             al[mm][0], al[mm][1], al[mm][2], al[mm][3], bh0, bh1);
                }
            }
        }
        __syncthreads();
    }

    // epilogue: split fp32 accumulators into bf16 hi/lo pairs
#pragma unroll
    for (int mm = 0; mm < 2; mm++) {
#pragma unroll
        for (int nn = 0; nn < 8; nn++) {
            int row = m0 + wm + mm * 16 + r;
            int col = n0 + wn + nn * 8 + c2;
            float v0 = acc[mm][nn][0], v1 = acc[mm][nn][1];
            uint32_t h01 = packbf(v0, v1);
            uint32_t l01 = packbf(v0 - __uint_as_float(h01 << 16),
                                  v1 - __uint_as_float(h01 & 0xFFFF0000u));
            *(uint32_t*)&yh[(size_t)row * D_ + col] = h01;
            *(uint32_t*)&yl[(size_t)row * D_ + col] = l01;
            float v2 = acc[mm][nn][2], v3 = acc[mm][nn][3];
            uint32_t h23 = packbf(v2, v3);
            uint32_t l23 = packbf(v2 - __uint_as_float(h23 << 16),
                                  v3 - __uint_as_float(h23 & 0xFFFF0000u));
            *(uint32_t*)&yh[(size_t)(row + 8) * D_ + col] = h23;
            *(uint32_t*)&yl[(size_t)(row + 8) * D_ + col] = l23;
        }
    }
}

// ===========================================================================
// Kernel 2: palace attention on tensor cores.
// CTA: 128 q-rows x full keys; 8 warps as 4(m) x 2(n). Per k-tile (128 keys):
// S = Q K^T (bf16 split x3), p = exp2poly(s*maskf) (no running max; scores
// bounded), P split in regs -> PV (x3) with V b-frags via ldmatrix.trans.
// K/V double-buffered cp.async. Final cross-warp O/l combine via smem.
// ===========================================================================
#define TB    18432              // one 128x72 bf16 tile
#define ROWB  144
#define ATTN_SMEM (10 * TB)      // Qh,Ql + 2 bufs x (Kh,Kl,Vh,Vl) = 184320

__global__ __launch_bounds__(256, 1) void palace_attn_tc(
    const float* __restrict__ wp, float* __restrict__ out)
{
    extern __shared__ __align__(128) char smem[];
    const uint32_t sb32 = smem_u32(smem);
    const int tid  = threadIdx.x;
    const int lane = tid & 31;
    const int wid  = tid >> 5;
    const int wm4  = wid >> 1;          // 0..3 -> rows wm4*32
    const int wn2  = wid & 1;           // 0..1 -> keys wn2*64
    const int r_   = lane >> 2;
    const int cq   = lane & 3;
    const int qt   = blockIdx.x;
    const int bh   = blockIdx.y;
    const int b    = bh >> 4;
    const int h    = bh & 15;

    const float sigw = 1.0f / (1.0f + expf(-wp[0]));
    const float cI = 0.125f * LOG2E;          // scale * log2(e)
    const float cX = cI * sigw;

    const int lrow  = tid >> 1;
    const int lhalf = tid & 1;
    const size_t grow_base = ((size_t)b * T_) * D_ + (size_t)h * 64 + lhalf * 32;

    auto ld4 = [&](uint32_t soff, const __nv_bfloat16* gp) {
#pragma unroll
        for (int kk = 0; kk < 4; kk++)
            cp16(sb32 + soff + lrow * ROWB + lhalf * 64 + kk * 16, gp + kk * 8);
    };
    // Q (once) + first K/V tile in group 0
    {
        const size_t go = grow_base + (size_t)(qt * 128 + lrow) * D_;
        ld4(0,  g_qh + go);
        ld4(TB, g_ql + go);
    }
    auto ldkv = [&](int buf, int kt) {
        const size_t go = grow_base + (size_t)(kt * 128 + lrow) * D_;
        const uint32_t off = 2 * TB + buf * 4 * TB;
        ld4(off,          g_kh + go);
        ld4(off + TB,     g_kl + go);
        ld4(off + 2 * TB, g_vh + go);
        ld4(off + 3 * TB, g_vl + go);
    };
    ldkv(0, 0);
    CP_COMMIT();

    float o[2][8][4];
    float lpart[2][2] = {{0.f, 0.f}, {0.f, 0.f}};
#pragma unroll
    for (int mm = 0; mm < 2; mm++)
#pragma unroll
        for (int j = 0; j < 8; j++)
#pragma unroll
            for (int c = 0; c < 4; c++) o[mm][j][c] = 0.f;

    const int arowb = wm4 * 32 + r_;
    const int krowb = wn2 * 64 + r_;
    const int vg = lane >> 3, vrr = lane & 7;
    const int vrow_off = wn2 * 64 + ((vg & 1) ? 8 : 0) + vrr;
    const int vcolB = ((vg >> 1) * 8) * 2;

    for (int kt = 0; kt < 16; kt++) {
        const int cur = kt & 1;
        if (kt + 1 < 16) { ldkv(cur ^ 1, kt + 1); CP_COMMIT(); CP_WAIT(1); }
        else             { CP_WAIT(0); }
        __syncthreads();

        const uint32_t KHo = 2 * TB + cur * 4 * TB;
        const uint32_t VHo = KHo + 2 * TB;

        // ---- S = Q K^T ----
        float s[2][8][4];
#pragma unroll
        for (int mm = 0; mm < 2; mm++)
#pragma unroll
            for (int j = 0; j < 8; j++)
#pragma unroll
                for (int c = 0; c < 4; c++) s[mm][j][c] = 0.f;

#pragma unroll
        for (int ks = 0; ks < 4; ks++) {
            const int cb = (ks * 16 + 2 * cq) * 2;
            uint32_t ah[2][4], al[2][4];
#pragma unroll
            for (int mm = 0; mm < 2; mm++) {
                const char* q0 = smem + (arowb + mm * 16) * ROWB + cb;
                ah[mm][0] = *(const uint32_t*)(q0);
                ah[mm][1] = *(const uint32_t*)(q0 + 8 * ROWB);
                ah[mm][2] = *(const uint32_t*)(q0 + 16);
                ah[mm][3] = *(const uint32_t*)(q0 + 8 * ROWB + 16);
                const char* q1 = q0 + TB;
                al[mm][0] = *(const uint32_t*)(q1);
                al[mm][1] = *(const uint32_t*)(q1 + 8 * ROWB);
                al[mm][2] = *(const uint32_t*)(q1 + 16);
                al[mm][3] = *(const uint32_t*)(q1 + 8 * ROWB + 16);
            }
#pragma unroll
            for (int j = 0; j < 8; j++) {
                const char* kp = smem + KHo + (krowb + j * 8) * ROWB + cb;
                uint32_t bh0 = *(const uint32_t*)(kp);
                uint32_t bh1 = *(const uint32_t*)(kp + 16);
                uint32_t bl0 = *(const uint32_t*)(kp + TB);
                uint32_t bl1 = *(const uint32_t*)(kp + TB + 16);
#pragma unroll
                for (int mm = 0; mm < 2; mm++) {
                    float* d = s[mm][j];
                    mma_bf16(d[0], d[1], d[2], d[3],
                             ah[mm][0], ah[mm][1], ah[mm][2], ah[mm][3], bh0, bh1);
                    mma_bf16(d[0], d[1], d[2], d[3],
                             ah[mm][0], ah[mm][1], ah[mm][2], ah[mm][3], bl0, bl1);
                    mma_bf16(d[0], d[1], d[2], d[3],
                             al[mm][0], al[mm][1], al[mm][2], al[mm][3], bh0, bh1);
                }
            }
        }

        // ---- softmax (no max) + PV per 16-key chunk ----
#pragma unroll
        for (int t = 0; t < 4; t++) {
            uint32_t ph[2][4], pl[2][4];
#pragma unroll
            for (int jj = 0; jj < 2; jj++) {
                const int j = 2 * t + jj;
#pragma unroll
                for (int mm = 0; mm < 2; mm++) {
                    const int blk0 = (wm4 & 1) * 4 + mm * 2;
#pragma unroll
                    for (int half = 0; half < 2; half++) {
                        const float mf = (j == blk0 + half) ? cI : cX;
                        float p0 = exp2p(s[mm][j][half * 2]     * mf);
                        float p1 = exp2p(s[mm][j][half * 2 + 1] * mf);
                        lpart[mm][half] += p0 + p1;
                        uint32_t hp = packbf(p0, p1);
                        uint32_t lp = packbf(p0 - __uint_as_float(hp << 16),
                                             p1 - __uint_as_float(hp & 0xFFFF0000u));
                        ph[mm][jj * 2 + half] = hp;
                        pl[mm][jj * 2 + half] = lp;
                    }
                }
            }
            const uint32_t va0 = sb32 + VHo + (vrow_off + t * 16) * ROWB + vcolB;
#pragma unroll
            for (int jnp = 0; jnp < 4; jnp++) {
                uint32_t vh0, vh1, vh2, vh3, vl0, vl1, vl2, vl3;
                ldsm4t(vh0, vh1, vh2, vh3, va0 + jnp * 32);
                ldsm4t(vl0, vl1, vl2, vl3, va0 + jnp * 32 + TB);
#pragma unroll
                for (int mm = 0; mm < 2; mm++) {
                    float* o0 = o[mm][jnp * 2];
                    mma_bf16(o0[0], o0[1], o0[2], o0[3],
                             ph[mm][0], ph[mm][1], ph[mm][2], ph[mm][3], vh0, vh1);
                    mma_bf16(o0[0], o0[1], o0[2], o0[3],
                             ph[mm][0], ph[mm][1], ph[mm][2], ph[mm][3], vl0, vl1);
                    mma_bf16(o0[0], o0[1], o0[2], o0[3],
                             pl[mm][0], pl[mm][1], pl[mm][2], pl[mm][3], vh0, vh1);
                    float* o1 = o[mm][jnp * 2 + 1];
                    mma_bf16(o1[0], o1[1], o1[2], o1[3],
                             ph[mm][0], ph[mm][1], ph[mm][2], ph[mm][3], vh2, vh3);
                    mma_bf16(o1[0], o1[1], o1[2], o1[3],
                             ph[mm][0], ph[mm][1], ph[mm][2], ph[mm][3], vl2, vl3);
                    mma_bf16(o1[0], o1[1], o1[2], o1[3],
                             pl[mm][0], pl[mm][1], pl[mm][2], pl[mm][3], vh2, vh3);
                }
            }
        }
        __syncthreads();
    }

    // ---- cross-warp combine (wn2 pairs share rows) ----
    float* Ost = (float*)(smem + 2 * TB);            // aliases dead K buf0
    float* Lst = (float*)(smem + 2 * TB + 128 * 68 * 4);
#pragma unroll
    for (int mm = 0; mm < 2; mm++)
#pragma unroll
        for (int half = 0; half < 2; half++) {
            float v = lpart[mm][half];
            v += __shfl_xor_sync(0xffffffffu, v, 1);
            v += __shfl_xor_sync(0xffffffffu, v, 2);
            lpart[mm][half] = v;
        }
    if (wn2 == 1) {
#pragma unroll
        for (int mm = 0; mm < 2; mm++) {
            int row = wm4 * 32 + mm * 16 + r_;
#pragma unroll
            for (int jn = 0; jn < 8; jn++) {
                int col = jn * 8 + 2 * cq;
                *(float2*)&Ost[row * 68 + col]       = make_float2(o[mm][jn][0], o[mm][jn][1]);
                *(float2*)&Ost[(row + 8) * 68 + col] = make_float2(o[mm][jn][2], o[mm][jn][3]);
            }
            if (cq == 0) {
                Lst[row]     = lpart[mm][0];
                Lst[row + 8] = lpart[mm][1];
            }
        }
    }
    __syncthreads();
    if (wn2 == 0) {
#pragma unroll
        for (int mm = 0; mm < 2; mm++) {
            int row = wm4 * 32 + mm * 16 + r_;
            float inv0 = 1.0f / (lpart[mm][0] + Lst[row]);
            float inv1 = 1.0f / (lpart[mm][1] + Lst[row + 8]);
            float* op0 = out + ((size_t)b * T_ + qt * 128 + row) * D_ + h * 64;
            float* op1 = op0 + 8 * D_;
#pragma unroll
            for (int jn = 0; jn < 8; jn++) {
                int col = jn * 8 + 2 * cq;
                float2 a0 = *(float2*)&Ost[row * 68 + col];
                float2 a1 = *(float2*)&Ost[(row + 8) * 68 + col];
                float2 w0 = make_float2((o[mm][jn][0] + a0.x) * inv0,
                                        (o[mm][jn][1] + a0.y) * inv0);
                float2 w1 = make_float2((o[mm][jn][2] + a1.x) * inv1,
                                        (o[mm][jn][3] + a1.y) * inv1);
                *(float2*)&op0[col] = w0;
                *(float2*)&op1[col] = w1;
            }
        }
    }
}

// ---------------------------------------------------------------------------
extern "C" void kernel_launch(void* const* d_in, const int* in_sizes, int n_in,
                              void* d_out, int out_size)
{
    const float* x  = (const float*)d_in[0];
    const float* Wq = (const float*)d_in[1];
    const float* Wk = (const float*)d_in[2];
    const float* Wv = (const float*)d_in[3];
    const float* wp = (const float*)d_in[4];
    float* out = (float*)d_out;

    __nv_bfloat16 *xh, *xl, *wh, *wl;
    cudaGetSymbolAddress((void**)&xh, g_xh);
    cudaGetSymbolAddress((void**)&xl, g_xl);
    cudaGetSymbolAddress((void**)&wh, g_wh);
    cudaGetSymbolAddress((void**)&wl, g_wl);

    cudaFuncSetAttribute(qkv_gemm_mma, cudaFuncAttributeMaxDynamicSharedMemorySize,
                         GEMM_SMEM);
    cudaFuncSetAttribute(palace_attn_tc, cudaFuncAttributeMaxDynamicSharedMemorySize,
                         ATTN_SMEM);

    int n4x = BT_ * D_ / 4;
    convert_split<<<(n4x + 255) / 256, 256>>>(x, xh, xl, n4x);
    int n4w = D_ * D_ / 4;
    convert_split<<<(n4w + 255) / 256, 256>>>(Wq, wh,                   wl,                   n4w);
    convert_split<<<(n4w + 255) / 256, 256>>>(Wk, wh + (size_t)D_ * D_, wl + (size_t)D_ * D_, n4w);
    convert_split<<<(n4w + 255) / 256, 256>>>(Wv, wh + 2ull * D_ * D_,  wl + 2ull * D_ * D_,  n4w);

    qkv_gemm_mma<<<dim3(8, 64, 3), 256, GEMM_SMEM>>>();
    palace_attn_tc<<<dim3(T_ / 128, B_ * H_), 256, ATTN_SMEM>>>(wp, out);
}

// round 7
// speedup vs baseline: 4.1594x; 1.3090x over previous
#include <cuda_runtime.h>
#include <cuda_bf16.h>
#include <cuda_fp16.h>
#include <cstdint>
#include <math.h>

#define B_  4
#define T_  2048
#define D_  1024
#define H_  16
#define BT_ (B_ * T_)
#define LOG2E 1.4426950408889634f

typedef unsigned long long u64;

// GEMM inputs: bf16 hi/lo split
__device__ __nv_bfloat16 g_xh[(size_t)BT_ * D_];
__device__ __nv_bfloat16 g_xl[(size_t)BT_ * D_];
__device__ __nv_bfloat16 g_wh[3ull * D_ * D_];
__device__ __nv_bfloat16 g_wl[3ull * D_ * D_];
// Attention operands: fp16 single
__device__ __half g_qf[(size_t)BT_ * D_];
__device__ __half g_kf[(size_t)BT_ * D_];
__device__ __half g_vf[(size_t)BT_ * D_];

// ---- portable PTX helpers (sm_80-era; ptxas target is plain sm_103) -------
__device__ __forceinline__ uint32_t smem_u32(const void* p) {
    uint32_t a;
    asm("{ .reg .u64 t; cvta.to.shared.u64 t, %1; cvt.u32.u64 %0, t; }"
        : "=r"(a) : "l"(p));
    return a;
}
__device__ __forceinline__ void cp16(uint32_t s, const void* g) {
    asm volatile("cp.async.cg.shared.global [%0], [%1], 16;"
                 :: "r"(s), "l"(g) : "memory");
}
#define CP_COMMIT() asm volatile("cp.async.commit_group;" ::: "memory")
#define CP_WAIT(n)  asm volatile("cp.async.wait_group %0;" :: "n"(n) : "memory")

__device__ __forceinline__ void mma_bf16(float& d0, float& d1, float& d2, float& d3,
                                         uint32_t a0, uint32_t a1, uint32_t a2, uint32_t a3,
                                         uint32_t b0, uint32_t b1) {
    asm volatile("mma.sync.aligned.m16n8k16.row.col.f32.bf16.bf16.f32 "
                 "{%0,%1,%2,%3},{%4,%5,%6,%7},{%8,%9},{%0,%1,%2,%3};"
                 : "+f"(d0), "+f"(d1), "+f"(d2), "+f"(d3)
                 : "r"(a0), "r"(a1), "r"(a2), "r"(a3), "r"(b0), "r"(b1));
}
__device__ __forceinline__ void mma_f16(float& d0, float& d1, float& d2, float& d3,
                                        uint32_t a0, uint32_t a1, uint32_t a2, uint32_t a3,
                                        uint32_t b0, uint32_t b1) {
    asm volatile("mma.sync.aligned.m16n8k16.row.col.f32.f16.f16.f32 "
                 "{%0,%1,%2,%3},{%4,%5,%6,%7},{%8,%9},{%0,%1,%2,%3};"
                 : "+f"(d0), "+f"(d1), "+f"(d2), "+f"(d3)
                 : "r"(a0), "r"(a1), "r"(a2), "r"(a3), "r"(b0), "r"(b1));
}
__device__ __forceinline__ void ldsm4t(uint32_t& r0, uint32_t& r1,
                                       uint32_t& r2, uint32_t& r3, uint32_t a) {
    asm volatile("ldmatrix.sync.aligned.m8n8.x4.trans.shared.b16 {%0,%1,%2,%3}, [%4];"
                 : "=r"(r0), "=r"(r1), "=r"(r2), "=r"(r3) : "r"(a));
}
__device__ __forceinline__ uint32_t packbf(float lo, float hi) {
    __nv_bfloat162 t = __floats2bfloat162_rn(lo, hi);
    return *(uint32_t*)&t;
}
// ---- packed f32x2 -----------------------------------------------------------
__device__ __forceinline__ u64 pk2(float lo, float hi) {
    u64 r; asm("mov.b64 %0,{%1,%2};" : "=l"(r) : "f"(lo), "f"(hi)); return r;
}
__device__ __forceinline__ void upk2(u64 v, float& lo, float& hi) {
    asm("mov.b64 {%0,%1},%2;" : "=f"(lo), "=f"(hi) : "l"(v));
}
__device__ __forceinline__ u64 fma2(u64 a, u64 b, u64 c) {
    u64 d; asm("fma.rn.f32x2 %0,%1,%2,%3;" : "=l"(d) : "l"(a), "l"(b), "l"(c)); return d;
}
__device__ __forceinline__ u64 mul2(u64 a, u64 b) {
    u64 d; asm("mul.rn.f32x2 %0,%1,%2;" : "=l"(d) : "l"(a), "l"(b)); return d;
}
__device__ __forceinline__ u64 add2(u64 a, u64 b) {
    u64 d; asm("add.rn.f32x2 %0,%1,%2;" : "=l"(d) : "l"(a), "l"(b)); return d;
}

// ===========================================================================
// Kernel 0: fp32 -> bf16 hi/lo split (GEMM inputs)
// ===========================================================================
__global__ __launch_bounds__(256) void convert_split(
    const float* __restrict__ src, __nv_bfloat16* __restrict__ hi,
    __nv_bfloat16* __restrict__ lo, int n4)
{
    int i = blockIdx.x * blockDim.x + threadIdx.x;
    if (i >= n4) return;
    float4 v = ((const float4*)src)[i];
    float vv[4] = {v.x, v.y, v.z, v.w};
    uint2 hp, lp;
    unsigned short* hu = (unsigned short*)&hp;
    unsigned short* lu = (unsigned short*)&lp;
#pragma unroll
    for (int j = 0; j < 4; j++) {
        __nv_bfloat16 h = __float2bfloat16(vv[j]);
        float hf = __bfloat162float(h);
        __nv_bfloat16 l = __float2bfloat16(vv[j] - hf);
        hu[j] = __bfloat16_as_ushort(h);
        lu[j] = __bfloat16_as_ushort(l);
    }
    ((uint2*)hi)[i] = hp;
    ((uint2*)lo)[i] = lp;
}

// ===========================================================================
// Kernel 1: QKV projection, mma.sync bf16 hi/lo split, fp32 accum.
// Epilogue writes q,k,v as fp16 for the attention kernel.
// ===========================================================================
#define TILE_E   (128 * 40)
#define TILE_B   (TILE_E * 2)
#define GEMM_SMEM (2 * 4 * TILE_B)

__global__ __launch_bounds__(256, 2) void qkv_gemm_mma()
{
    extern __shared__ __align__(16) char smem[];
    __nv_bfloat16* sb = (__nv_bfloat16*)smem;
    const uint32_t sbase = smem_u32(smem);

    const int tid  = threadIdx.x;
    const int lane = tid & 31;
    const int wid  = tid >> 5;
    const int wm   = (wid >> 1) * 32;
    const int wn   = (wid & 1) * 64;
    const int n0   = blockIdx.x * 128;
    const int m0   = blockIdx.y * 128;
    const int mat  = blockIdx.z;

    const __nv_bfloat16* Ah_g = g_xh + (size_t)m0 * D_;
    const __nv_bfloat16* Al_g = g_xl + (size_t)m0 * D_;
    const __nv_bfloat16* Bh_g = g_wh + (size_t)mat * D_ * D_ + (size_t)n0 * D_;
    const __nv_bfloat16* Bl_g = g_wl + (size_t)mat * D_ * D_ + (size_t)n0 * D_;
    __half* yf = (mat == 0) ? g_qf : ((mat == 1) ? g_kf : g_vf);

    const int lrow  = tid >> 1;
    const int lhalf = tid & 1;

    float acc[2][8][4];
#pragma unroll
    for (int i = 0; i < 2; i++)
#pragma unroll
        for (int j = 0; j < 8; j++)
#pragma unroll
            for (int c = 0; c < 4; c++) acc[i][j][c] = 0.0f;

    const int r  = lane >> 2;
    const int c2 = (lane & 3) * 2;

    auto load_tiles = [&](int buf, int k0) {
        const size_t go = (size_t)lrow * D_ + k0 + lhalf * 16;
        const uint32_t so = sbase + buf * 4 * TILE_B + lrow * 80 + lhalf * 32;
        cp16(so + 0 * TILE_B,      Ah_g + go);
        cp16(so + 0 * TILE_B + 16, Ah_g + go + 8);
        cp16(so + 1 * TILE_B,      Al_g + go);
        cp16(so + 1 * TILE_B + 16, Al_g + go + 8);
        cp16(so + 2 * TILE_B,      Bh_g + go);
        cp16(so + 2 * TILE_B + 16, Bh_g + go + 8);
        cp16(so + 3 * TILE_B,      Bl_g + go);
        cp16(so + 3 * TILE_B + 16, Bl_g + go + 8);
    };

    load_tiles(0, 0);
    CP_COMMIT();

    for (int it = 0; it < 32; it++) {
        const int cur = it & 1;
        if (it + 1 < 32) {
            load_tiles(cur ^ 1, (it + 1) * 32);
            CP_COMMIT();
            CP_WAIT(1);
        } else {
            CP_WAIT(0);
        }
        __syncthreads();

        const __nv_bfloat16* Ah = sb + (cur * 4 + 0) * TILE_E;
        const __nv_bfloat16* Al = sb + (cur * 4 + 1) * TILE_E;
        const __nv_bfloat16* Bh = sb + (cur * 4 + 2) * TILE_E;
        const __nv_bfloat16* Bl = sb + (cur * 4 + 3) * TILE_E;

#pragma unroll
        for (int ks = 0; ks < 2; ks++) {
            const int kof = ks * 16;
            uint32_t ah[2][4], al[2][4];
#pragma unroll
            for (int mm = 0; mm < 2; mm++) {
                int row0 = wm + mm * 16 + r;
                const __nv_bfloat16* p = Ah + row0 * 40 + kof + c2;
                ah[mm][0] = *(const uint32_t*)(p);
                ah[mm][1] = *(const uint32_t*)(p + 8 * 40);
                ah[mm][2] = *(const uint32_t*)(p + 8);
                ah[mm][3] = *(const uint32_t*)(p + 8 * 40 + 8);
                const __nv_bfloat16* q = Al + row0 * 40 + kof + c2;
                al[mm][0] = *(const uint32_t*)(q);
                al[mm][1] = *(const uint32_t*)(q + 8 * 40);
                al[mm][2] = *(const uint32_t*)(q + 8);
                al[mm][3] = *(const uint32_t*)(q + 8 * 40 + 8);
            }
#pragma unroll
            for (int nn = 0; nn < 8; nn++) {
                int nrow = wn + nn * 8 + r;
                const __nv_bfloat16* pb = Bh + nrow * 40 + kof + c2;
                uint32_t bh0 = *(const uint32_t*)(pb);
                uint32_t bh1 = *(const uint32_t*)(pb + 8);
                const __nv_bfloat16* qb = Bl + nrow * 40 + kof + c2;
                uint32_t bl0 = *(const uint32_t*)(qb);
                uint32_t bl1 = *(const uint32_t*)(qb + 8);
#pragma unroll
                for (int mm = 0; mm < 2; mm++) {
                    float* d = acc[mm][nn];
                    mma_bf16(d[0], d[1], d[2], d[3],
                             ah[mm][0], ah[mm][1], ah[mm][2], ah[mm][3], bh0, bh1);
                    mma_bf16(d[0], d[1], d[2], d[3],
                             ah[mm][0], ah[mm][1], ah[mm][2], ah[mm][3], bl0, bl1);
                    mma_bf16(d[0], d[1], d[2], d[3],
                             al[mm][0], al[mm][1], al[mm][2], al[mm][3], bh0, bh1);
                }
            }
        }
        __syncthreads();
    }

    // epilogue: fp16 outputs for attention
#pragma unroll
    for (int mm = 0; mm < 2; mm++) {
#pragma unroll
        for (int nn = 0; nn < 8; nn++) {
            int row = m0 + wm + mm * 16 + r;
            int col = n0 + wn + nn * 8 + c2;
            __half2 h01 = __floats2half2_rn(acc[mm][nn][0], acc[mm][nn][1]);
            *(uint32_t*)&yf[(size_t)row * D_ + col] = *(uint32_t*)&h01;
            __half2 h23 = __floats2half2_rn(acc[mm][nn][2], acc[mm][nn][3]);
            *(uint32_t*)&yf[(size_t)(row + 8) * D_ + col] = *(uint32_t*)&h23;
        }
    }
}

// ===========================================================================
// Kernel 2: palace attention, fp16 tensor cores.
// QK: single fp16 MMA. PV: P split (ph+pl fp16) x single fp16 V -> 2 MMAs.
// exp2 via packed f32x2 polynomial. 8 warps 4(m)x2(n), 128x128 tiles,
// double-buffered cp.async K/V. Smem 5 tiles x 18432B = 92160.
// ===========================================================================
#define TB    18432              // 128 rows x 144B (64 fp16 + 16B pad)
#define ROWB  144
#define ATTN_SMEM (5 * TB)

__global__ __launch_bounds__(256, 1) void palace_attn_tc(
    const float* __restrict__ wp, float* __restrict__ out)
{
    extern __shared__ __align__(128) char smem[];
    const uint32_t sb32 = smem_u32(smem);
    const int tid  = threadIdx.x;
    const int lane = tid & 31;
    const int wid  = tid >> 5;
    const int wm4  = wid >> 1;
    const int wn2  = wid & 1;
    const int r_   = lane >> 2;
    const int cq   = lane & 3;
    const int qt   = blockIdx.x;
    const int bh   = blockIdx.y;
    const int b    = bh >> 4;
    const int h    = bh & 15;

    const float sigw = 1.0f / (1.0f + expf(-wp[0]));
    const float cI = 0.125f * LOG2E;
    const float cX = cI * sigw;
    const u64 cI2 = pk2(cI, cI), cX2 = pk2(cX, cX);
    const u64 magic2  = pk2(12582912.0f, 12582912.0f);
    const u64 nmagic2 = pk2(-12582912.0f, -12582912.0f);
    const u64 neg1_2  = pk2(-1.0f, -1.0f);
    const u64 C0 = pk2(1.5403530e-4f, 1.5403530e-4f);
    const u64 C1 = pk2(1.3333558e-3f, 1.3333558e-3f);
    const u64 C2 = pk2(9.6181291e-3f, 9.6181291e-3f);
    const u64 C3 = pk2(5.5504109e-2f, 5.5504109e-2f);
    const u64 C4 = pk2(2.4022651e-1f, 2.4022651e-1f);
    const u64 C5 = pk2(6.9314718e-1f, 6.9314718e-1f);
    const u64 C6 = pk2(1.0f, 1.0f);

    const int lrow  = tid >> 1;
    const int lhalf = tid & 1;
    const size_t grow_base = ((size_t)b * T_) * D_ + (size_t)h * 64 + lhalf * 32;

    auto ld4 = [&](uint32_t soff, const __half* gp) {
#pragma unroll
        for (int kk = 0; kk < 4; kk++)
            cp16(sb32 + soff + lrow * ROWB + lhalf * 64 + kk * 16, gp + kk * 8);
    };
    {
        const size_t go = grow_base + (size_t)(qt * 128 + lrow) * D_;
        ld4(0, g_qf + go);
    }
    auto ldkv = [&](int buf, int kt) {
        const size_t go = grow_base + (size_t)(kt * 128 + lrow) * D_;
        const uint32_t off = TB + buf * 2 * TB;
        ld4(off,      g_kf + go);
        ld4(off + TB, g_vf + go);
    };
    ldkv(0, 0);
    CP_COMMIT();

    float o[2][8][4];
    u64 lp2[2][2] = {{0ull, 0ull}, {0ull, 0ull}};
#pragma unroll
    for (int mm = 0; mm < 2; mm++)
#pragma unroll
        for (int j = 0; j < 8; j++)
#pragma unroll
            for (int c = 0; c < 4; c++) o[mm][j][c] = 0.f;

    const int arowb = wm4 * 32 + r_;
    const int krowb = wn2 * 64 + r_;
    const int vg = lane >> 3, vrr = lane & 7;
    const int vrow_off = wn2 * 64 + ((vg & 1) ? 8 : 0) + vrr;
    const int vcolB = ((vg >> 1) * 8) * 2;
    const int blk0base = (wm4 & 1) * 4;

    for (int kt = 0; kt < 16; kt++) {
        const int cur = kt & 1;
        if (kt + 1 < 16) { ldkv(cur ^ 1, kt + 1); CP_COMMIT(); CP_WAIT(1); }
        else             { CP_WAIT(0); }
        __syncthreads();

        const uint32_t KHo = TB + cur * 2 * TB;
        const uint32_t VHo = KHo + TB;

        // ---- S = Q K^T (single fp16) ----
        float s[2][8][4];
#pragma unroll
        for (int mm = 0; mm < 2; mm++)
#pragma unroll
            for (int j = 0; j < 8; j++)
#pragma unroll
                for (int c = 0; c < 4; c++) s[mm][j][c] = 0.f;

#pragma unroll
        for (int ks = 0; ks < 4; ks++) {
            const int cb = (ks * 16 + 2 * cq) * 2;
            uint32_t aq[2][4];
#pragma unroll
            for (int mm = 0; mm < 2; mm++) {
                const char* q0 = smem + (arowb + mm * 16) * ROWB + cb;
                aq[mm][0] = *(const uint32_t*)(q0);
                aq[mm][1] = *(const uint32_t*)(q0 + 8 * ROWB);
                aq[mm][2] = *(const uint32_t*)(q0 + 16);
                aq[mm][3] = *(const uint32_t*)(q0 + 8 * ROWB + 16);
            }
#pragma unroll
            for (int j = 0; j < 8; j++) {
                const char* kp = smem + KHo + (krowb + j * 8) * ROWB + cb;
                uint32_t b0 = *(const uint32_t*)(kp);
                uint32_t b1 = *(const uint32_t*)(kp + 16);
#pragma unroll
                for (int mm = 0; mm < 2; mm++) {
                    float* d = s[mm][j];
                    mma_f16(d[0], d[1], d[2], d[3],
                            aq[mm][0], aq[mm][1], aq[mm][2], aq[mm][3], b0, b1);
                }
            }
        }

        // ---- packed exp2 softmax + PV per 16-key chunk ----
#pragma unroll
        for (int t = 0; t < 4; t++) {
            uint32_t ph[2][4], pl[2][4];
#pragma unroll
            for (int jj = 0; jj < 2; jj++) {
                const int j = 2 * t + jj;
#pragma unroll
                for (int mm = 0; mm < 2; mm++) {
                    const int blk0 = blk0base + mm * 2;
#pragma unroll
                    for (int half = 0; half < 2; half++) {
                        const u64 mf2 = (j == blk0 + half) ? cI2 : cX2;
                        u64 s2 = pk2(s[mm][j][half * 2], s[mm][j][half * 2 + 1]);
                        u64 x2 = mul2(s2, mf2);
                        u64 t2 = add2(x2, magic2);
                        u64 n2 = add2(t2, nmagic2);
                        u64 f2 = fma2(n2, neg1_2, x2);
                        u64 p2 = fma2(C0, f2, C1);
                        p2 = fma2(p2, f2, C2);
                        p2 = fma2(p2, f2, C3);
                        p2 = fma2(p2, f2, C4);
                        p2 = fma2(p2, f2, C5);
                        p2 = fma2(p2, f2, C6);
                        uint32_t tl = (uint32_t)t2, th = (uint32_t)(t2 >> 32);
                        const uint32_t KC = 0x4B400000u - 127u;
                        uint32_t sl = (tl - KC) << 23;
                        uint32_t sh = (th - KC) << 23;
                        u64 sc2 = ((u64)sh << 32) | (u64)sl;
                        u64 pe = mul2(p2, sc2);
                        lp2[mm][half] = add2(lp2[mm][half], pe);
                        float p0, p1; upk2(pe, p0, p1);
                        __half2 h2 = __floats2half2_rn(p0, p1);
                        ph[mm][jj * 2 + half] = *(uint32_t*)&h2;
                        float2 hf = __half22float2(h2);
                        u64 pl2v = fma2(pk2(hf.x, hf.y), neg1_2, pe);
                        float l0, l1; upk2(pl2v, l0, l1);
                        __half2 lh2 = __floats2half2_rn(l0, l1);
                        pl[mm][jj * 2 + half] = *(uint32_t*)&lh2;
                    }
                }
            }
            const uint32_t va0 = sb32 + VHo + (vrow_off + t * 16) * ROWB + vcolB;
#pragma unroll
            for (int jnp = 0; jnp < 4; jnp++) {
                uint32_t v0, v1, v2, v3;
                ldsm4t(v0, v1, v2, v3, va0 + jnp * 32);
#pragma unroll
                for (int mm = 0; mm < 2; mm++) {
                    float* o0 = o[mm][jnp * 2];
                    mma_f16(o0[0], o0[1], o0[2], o0[3],
                            ph[mm][0], ph[mm][1], ph[mm][2], ph[mm][3], v0, v1);
                    mma_f16(o0[0], o0[1], o0[2], o0[3],
                            pl[mm][0], pl[mm][1], pl[mm][2], pl[mm][3], v0, v1);
                    float* o1 = o[mm][jnp * 2 + 1];
                    mma_f16(o1[0], o1[1], o1[2], o1[3],
                            ph[mm][0], ph[mm][1], ph[mm][2], ph[mm][3], v2, v3);
                    mma_f16(o1[0], o1[1], o1[2], o1[3],
                            pl[mm][0], pl[mm][1], pl[mm][2], pl[mm][3], v2, v3);
                }
            }
        }
        __syncthreads();
    }

    // ---- cross-warp combine ----
    float lpart[2][2];
#pragma unroll
    for (int mm = 0; mm < 2; mm++)
#pragma unroll
        for (int half = 0; half < 2; half++) {
            float a, bb; upk2(lp2[mm][half], a, bb);
            float v = a + bb;
            v += __shfl_xor_sync(0xffffffffu, v, 1);
            v += __shfl_xor_sync(0xffffffffu, v, 2);
            lpart[mm][half] = v;
        }
    float* Ost = (float*)(smem + TB);
    float* Lst = (float*)(smem + TB + 128 * 68 * 4);
    if (wn2 == 1) {
#pragma unroll
        for (int mm = 0; mm < 2; mm++) {
            int row = wm4 * 32 + mm * 16 + r_;
#pragma unroll
            for (int jn = 0; jn < 8; jn++) {
                int col = jn * 8 + 2 * cq;
                *(float2*)&Ost[row * 68 + col]       = make_float2(o[mm][jn][0], o[mm][jn][1]);
                *(float2*)&Ost[(row + 8) * 68 + col] = make_float2(o[mm][jn][2], o[mm][jn][3]);
            }
            if (cq == 0) {
                Lst[row]     = lpart[mm][0];
                Lst[row + 8] = lpart[mm][1];
            }
        }
    }
    __syncthreads();
    if (wn2 == 0) {
#pragma unroll
        for (int mm = 0; mm < 2; mm++) {
            int row = wm4 * 32 + mm * 16 + r_;
            float inv0 = 1.0f / (lpart[mm][0] + Lst[row]);
            float inv1 = 1.0f / (lpart[mm][1] + Lst[row + 8]);
            float* op0 = out + ((size_t)b * T_ + qt * 128 + row) * D_ + h * 64;
            float* op1 = op0 + 8 * D_;
#pragma unroll
            for (int jn = 0; jn < 8; jn++) {
                int col = jn * 8 + 2 * cq;
                float2 a0 = *(float2*)&Ost[row * 68 + col];
                float2 a1 = *(float2*)&Ost[(row + 8) * 68 + col];
                float2 w0 = make_float2((o[mm][jn][0] + a0.x) * inv0,
                                        (o[mm][jn][1] + a0.y) * inv0);
                float2 w1 = make_float2((o[mm][jn][2] + a1.x) * inv1,
                                        (o[mm][jn][3] + a1.y) * inv1);
                *(float2*)&op0[col] = w0;
                *(float2*)&op1[col] = w1;
            }
        }
    }
}

// ---------------------------------------------------------------------------
extern "C" void kernel_launch(void* const* d_in, const int* in_sizes, int n_in,
                              void* d_out, int out_size)
{
    const float* x  = (const float*)d_in[0];
    const float* Wq = (const float*)d_in[1];
    const float* Wk = (const float*)d_in[2];
    const float* Wv = (const float*)d_in[3];
    const float* wp = (const float*)d_in[4];
    float* out = (float*)d_out;

    __nv_bfloat16 *xh, *xl, *wh, *wl;
    cudaGetSymbolAddress((void**)&xh, g_xh);
    cudaGetSymbolAddress((void**)&xl, g_xl);
    cudaGetSymbolAddress((void**)&wh, g_wh);
    cudaGetSymbolAddress((void**)&wl, g_wl);

    cudaFuncSetAttribute(qkv_gemm_mma, cudaFuncAttributeMaxDynamicSharedMemorySize,
                         GEMM_SMEM);
    cudaFuncSetAttribute(palace_attn_tc, cudaFuncAttributeMaxDynamicSharedMemorySize,
                         ATTN_SMEM);

    int n4x = BT_ * D_ / 4;
    convert_split<<<(n4x + 255) / 256, 256>>>(x, xh, xl, n4x);
    int n4w = D_ * D_ / 4;
    convert_split<<<(n4w + 255) / 256, 256>>>(Wq, wh,                   wl,                   n4w);
    convert_split<<<(n4w + 255) / 256, 256>>>(Wk, wh + (size_t)D_ * D_, wl + (size_t)D_ * D_, n4w);
    convert_split<<<(n4w + 255) / 256, 256>>>(Wv, wh + 2ull * D_ * D_,  wl + 2ull * D_ * D_,  n4w);

    qkv_gemm_mma<<<dim3(8, 64, 3), 256, GEMM_SMEM>>>();
    palace_attn_tc<<<dim3(T_ / 128, B_ * H_), 256, ATTN_SMEM>>>(wp, out);
}

// round 8
// speedup vs baseline: 5.6062x; 1.3478x over previous
#include <cuda_runtime.h>
#include <cuda_bf16.h>
#include <cuda_fp16.h>
#include <cstdint>
#include <math.h>

#define B_  4
#define T_  2048
#define D_  1024
#define H_  16
#define BT_ (B_ * T_)
#define LOG2E 1.4426950408889634f

typedef unsigned long long u64;

// GEMM inputs: x split into fp16 hi/lo, W single fp16
__device__ __half g_xh[(size_t)BT_ * D_];
__device__ __half g_xl[(size_t)BT_ * D_];
__device__ __half g_wf[3ull * D_ * D_];
// Attention operands: fp16
__device__ __half g_qf[(size_t)BT_ * D_];
__device__ __half g_kf[(size_t)BT_ * D_];
__device__ __half g_vf[(size_t)BT_ * D_];

// ---- portable PTX helpers (sm_80-era; ptxas target is plain sm_103) -------
__device__ __forceinline__ uint32_t smem_u32(const void* p) {
    uint32_t a;
    asm("{ .reg .u64 t; cvta.to.shared.u64 t, %1; cvt.u32.u64 %0, t; }"
        : "=r"(a) : "l"(p));
    return a;
}
__device__ __forceinline__ void cp16(uint32_t s, const void* g) {
    asm volatile("cp.async.cg.shared.global [%0], [%1], 16;"
                 :: "r"(s), "l"(g) : "memory");
}
#define CP_COMMIT() asm volatile("cp.async.commit_group;" ::: "memory")
#define CP_WAIT(n)  asm volatile("cp.async.wait_group %0;" :: "n"(n) : "memory")

__device__ __forceinline__ void mma_f16(float& d0, float& d1, float& d2, float& d3,
                                        uint32_t a0, uint32_t a1, uint32_t a2, uint32_t a3,
                                        uint32_t b0, uint32_t b1) {
    asm volatile("mma.sync.aligned.m16n8k16.row.col.f32.f16.f16.f32 "
                 "{%0,%1,%2,%3},{%4,%5,%6,%7},{%8,%9},{%0,%1,%2,%3};"
                 : "+f"(d0), "+f"(d1), "+f"(d2), "+f"(d3)
                 : "r"(a0), "r"(a1), "r"(a2), "r"(a3), "r"(b0), "r"(b1));
}
__device__ __forceinline__ void ldsm4t(uint32_t& r0, uint32_t& r1,
                                       uint32_t& r2, uint32_t& r3, uint32_t a) {
    asm volatile("ldmatrix.sync.aligned.m8n8.x4.trans.shared.b16 {%0,%1,%2,%3}, [%4];"
                 : "=r"(r0), "=r"(r1), "=r"(r2), "=r"(r3) : "r"(a));
}
// ---- packed f32x2 -----------------------------------------------------------
__device__ __forceinline__ u64 pk2(float lo, float hi) {
    u64 r; asm("mov.b64 %0,{%1,%2};" : "=l"(r) : "f"(lo), "f"(hi)); return r;
}
__device__ __forceinline__ void upk2(u64 v, float& lo, float& hi) {
    asm("mov.b64 {%0,%1},%2;" : "=f"(lo), "=f"(hi) : "l"(v));
}
__device__ __forceinline__ u64 fma2(u64 a, u64 b, u64 c) {
    u64 d; asm("fma.rn.f32x2 %0,%1,%2,%3;" : "=l"(d) : "l"(a), "l"(b), "l"(c)); return d;
}
__device__ __forceinline__ u64 mul2(u64 a, u64 b) {
    u64 d; asm("mul.rn.f32x2 %0,%1,%2;" : "=l"(d) : "l"(a), "l"(b)); return d;
}
__device__ __forceinline__ u64 add2(u64 a, u64 b) {
    u64 d; asm("add.rn.f32x2 %0,%1,%2;" : "=l"(d) : "l"(a), "l"(b)); return d;
}

// ===========================================================================
// Kernel 0a: fp32 -> fp16 hi/lo split (x)
// ===========================================================================
__global__ __launch_bounds__(256) void convert_split_h(
    const float* __restrict__ src, __half* __restrict__ hi,
    __half* __restrict__ lo, int n4)
{
    int i = blockIdx.x * blockDim.x + threadIdx.x;
    if (i >= n4) return;
    float4 v = ((const float4*)src)[i];
    float vv[4] = {v.x, v.y, v.z, v.w};
    uint2 hp, lp;
    unsigned short* hu = (unsigned short*)&hp;
    unsigned short* lu = (unsigned short*)&lp;
#pragma unroll
    for (int j = 0; j < 4; j++) {
        __half h = __float2half_rn(vv[j]);
        float hf = __half2float(h);
        __half l = __float2half_rn(vv[j] - hf);
        hu[j] = __half_as_ushort(h);
        lu[j] = __half_as_ushort(l);
    }
    ((uint2*)hi)[i] = hp;
    ((uint2*)lo)[i] = lp;
}

// Kernel 0b: fp32 -> single fp16 (W)
__global__ __launch_bounds__(256) void convert_h(
    const float* __restrict__ src, __half* __restrict__ dst, int n4)
{
    int i = blockIdx.x * blockDim.x + threadIdx.x;
    if (i >= n4) return;
    float4 v = ((const float4*)src)[i];
    uint2 hp;
    unsigned short* hu = (unsigned short*)&hp;
    hu[0] = __half_as_ushort(__float2half_rn(v.x));
    hu[1] = __half_as_ushort(__float2half_rn(v.y));
    hu[2] = __half_as_ushort(__float2half_rn(v.z));
    hu[3] = __half_as_ushort(__float2half_rn(v.w));
    ((uint2*)dst)[i] = hp;
}

// ===========================================================================
// Kernel 1: QKV projection, mma.sync fp16: y = (xh + xl) @ fp16(W)^T.
// 2 MMAs per position (hh + lh), fp32 accum. Epilogue writes fp16 q/k/v.
// ===========================================================================
#define TILE_E   (128 * 40)
#define TILE_B   (TILE_E * 2)          // 10240 B
#define GEMM_SMEM (2 * 3 * TILE_B)     // 61440 B

__global__ __launch_bounds__(256, 2) void qkv_gemm_mma()
{
    extern __shared__ __align__(16) char smem[];
    __half* sb = (__half*)smem;
    const uint32_t sbase = smem_u32(smem);

    const int tid  = threadIdx.x;
    const int lane = tid & 31;
    const int wid  = tid >> 5;
    const int wm   = (wid >> 1) * 32;
    const int wn   = (wid & 1) * 64;
    const int n0   = blockIdx.x * 128;
    const int m0   = blockIdx.y * 128;
    const int mat  = blockIdx.z;

    const __half* Ah_g = g_xh + (size_t)m0 * D_;
    const __half* Al_g = g_xl + (size_t)m0 * D_;
    const __half* Bh_g = g_wf + (size_t)mat * D_ * D_ + (size_t)n0 * D_;
    __half* yf = (mat == 0) ? g_qf : ((mat == 1) ? g_kf : g_vf);

    const int lrow  = tid >> 1;
    const int lhalf = tid & 1;

    float acc[2][8][4];
#pragma unroll
    for (int i = 0; i < 2; i++)
#pragma unroll
        for (int j = 0; j < 8; j++)
#pragma unroll
            for (int c = 0; c < 4; c++) acc[i][j][c] = 0.0f;

    const int r  = lane >> 2;
    const int c2 = (lane & 3) * 2;

    auto load_tiles = [&](int buf, int k0) {
        const size_t go = (size_t)lrow * D_ + k0 + lhalf * 16;
        const uint32_t so = sbase + buf * 3 * TILE_B + lrow * 80 + lhalf * 32;
        cp16(so + 0 * TILE_B,      Ah_g + go);
        cp16(so + 0 * TILE_B + 16, Ah_g + go + 8);
        cp16(so + 1 * TILE_B,      Al_g + go);
        cp16(so + 1 * TILE_B + 16, Al_g + go + 8);
        cp16(so + 2 * TILE_B,      Bh_g + go);
        cp16(so + 2 * TILE_B + 16, Bh_g + go + 8);
    };

    load_tiles(0, 0);
    CP_COMMIT();

    for (int it = 0; it < 32; it++) {
        const int cur = it & 1;
        if (it + 1 < 32) {
            load_tiles(cur ^ 1, (it + 1) * 32);
            CP_COMMIT();
            CP_WAIT(1);
        } else {
            CP_WAIT(0);
        }
        __syncthreads();

        const __half* Ah = sb + (cur * 3 + 0) * TILE_E;
        const __half* Al = sb + (cur * 3 + 1) * TILE_E;
        const __half* Bh = sb + (cur * 3 + 2) * TILE_E;

#pragma unroll
        for (int ks = 0; ks < 2; ks++) {
            const int kof = ks * 16;
            uint32_t ah[2][4], al[2][4];
#pragma unroll
            for (int mm = 0; mm < 2; mm++) {
                int row0 = wm + mm * 16 + r;
                const __half* p = Ah + row0 * 40 + kof + c2;
                ah[mm][0] = *(const uint32_t*)(p);
                ah[mm][1] = *(const uint32_t*)(p + 8 * 40);
                ah[mm][2] = *(const uint32_t*)(p + 8);
                ah[mm][3] = *(const uint32_t*)(p + 8 * 40 + 8);
                const __half* q = Al + row0 * 40 + kof + c2;
                al[mm][0] = *(const uint32_t*)(q);
                al[mm][1] = *(const uint32_t*)(q + 8 * 40);
                al[mm][2] = *(const uint32_t*)(q + 8);
                al[mm][3] = *(const uint32_t*)(q + 8 * 40 + 8);
            }
#pragma unroll
            for (int nn = 0; nn < 8; nn++) {
                int nrow = wn + nn * 8 + r;
                const __half* pb = Bh + nrow * 40 + kof + c2;
                uint32_t b0 = *(const uint32_t*)(pb);
                uint32_t b1 = *(const uint32_t*)(pb + 8);
#pragma unroll
                for (int mm = 0; mm < 2; mm++) {
                    float* d = acc[mm][nn];
                    mma_f16(d[0], d[1], d[2], d[3],
                            ah[mm][0], ah[mm][1], ah[mm][2], ah[mm][3], b0, b1);
                    mma_f16(d[0], d[1], d[2], d[3],
                            al[mm][0], al[mm][1], al[mm][2], al[mm][3], b0, b1);
                }
            }
        }
        __syncthreads();
    }

    // epilogue: fp16 outputs for attention
#pragma unroll
    for (int mm = 0; mm < 2; mm++) {
#pragma unroll
        for (int nn = 0; nn < 8; nn++) {
            int row = m0 + wm + mm * 16 + r;
            int col = n0 + wn + nn * 8 + c2;
            __half2 h01 = __floats2half2_rn(acc[mm][nn][0], acc[mm][nn][1]);
            *(uint32_t*)&yf[(size_t)row * D_ + col] = *(uint32_t*)&h01;
            __half2 h23 = __floats2half2_rn(acc[mm][nn][2], acc[mm][nn][3]);
            *(uint32_t*)&yf[(size_t)(row + 8) * D_ + col] = *(uint32_t*)&h23;
        }
    }
}

// ===========================================================================
// Kernel 2: palace attention, fp16 tensor cores.
// QK: 1 fp16 MMA. PV: 1 fp16 MMA (P single fp16).
// exp2 via packed f32x2 polynomial. 8 warps 4(m)x2(n), 128x128 tiles,
// double-buffered cp.async K/V.
// ===========================================================================
#define TB    18432              // 128 rows x 144B (64 fp16 + 16B pad)
#define ROWB  144
#define ATTN_SMEM (5 * TB)

__global__ __launch_bounds__(256, 1) void palace_attn_tc(
    const float* __restrict__ wp, float* __restrict__ out)
{
    extern __shared__ __align__(128) char smem[];
    const uint32_t sb32 = smem_u32(smem);
    const int tid  = threadIdx.x;
    const int lane = tid & 31;
    const int wid  = tid >> 5;
    const int wm4  = wid >> 1;
    const int wn2  = wid & 1;
    const int r_   = lane >> 2;
    const int cq   = lane & 3;
    const int qt   = blockIdx.x;
    const int bh   = blockIdx.y;
    const int b    = bh >> 4;
    const int h    = bh & 15;

    const float sigw = 1.0f / (1.0f + expf(-wp[0]));
    const float cI = 0.125f * LOG2E;
    const float cX = cI * sigw;
    const u64 cI2 = pk2(cI, cI), cX2 = pk2(cX, cX);
    const u64 magic2  = pk2(12582912.0f, 12582912.0f);
    const u64 nmagic2 = pk2(-12582912.0f, -12582912.0f);
    const u64 neg1_2  = pk2(-1.0f, -1.0f);
    const u64 C0 = pk2(1.5403530e-4f, 1.5403530e-4f);
    const u64 C1 = pk2(1.3333558e-3f, 1.3333558e-3f);
    const u64 C2 = pk2(9.6181291e-3f, 9.6181291e-3f);
    const u64 C3 = pk2(5.5504109e-2f, 5.5504109e-2f);
    const u64 C4 = pk2(2.4022651e-1f, 2.4022651e-1f);
    const u64 C5 = pk2(6.9314718e-1f, 6.9314718e-1f);
    const u64 C6 = pk2(1.0f, 1.0f);

    const int lrow  = tid >> 1;
    const int lhalf = tid & 1;
    const size_t grow_base = ((size_t)b * T_) * D_ + (size_t)h * 64 + lhalf * 32;

    auto ld4 = [&](uint32_t soff, const __half* gp) {
#pragma unroll
        for (int kk = 0; kk < 4; kk++)
            cp16(sb32 + soff + lrow * ROWB + lhalf * 64 + kk * 16, gp + kk * 8);
    };
    {
        const size_t go = grow_base + (size_t)(qt * 128 + lrow) * D_;
        ld4(0, g_qf + go);
    }
    auto ldkv = [&](int buf, int kt) {
        const size_t go = grow_base + (size_t)(kt * 128 + lrow) * D_;
        const uint32_t off = TB + buf * 2 * TB;
        ld4(off,      g_kf + go);
        ld4(off + TB, g_vf + go);
    };
    ldkv(0, 0);
    CP_COMMIT();

    float o[2][8][4];
    u64 lp2[2][2] = {{0ull, 0ull}, {0ull, 0ull}};
#pragma unroll
    for (int mm = 0; mm < 2; mm++)
#pragma unroll
        for (int j = 0; j < 8; j++)
#pragma unroll
            for (int c = 0; c < 4; c++) o[mm][j][c] = 0.f;

    const int arowb = wm4 * 32 + r_;
    const int krowb = wn2 * 64 + r_;
    const int vg = lane >> 3, vrr = lane & 7;
    const int vrow_off = wn2 * 64 + ((vg & 1) ? 8 : 0) + vrr;
    const int vcolB = ((vg >> 1) * 8) * 2;
    const int blk0base = (wm4 & 1) * 4;

    for (int kt = 0; kt < 16; kt++) {
        const int cur = kt & 1;
        if (kt + 1 < 16) { ldkv(cur ^ 1, kt + 1); CP_COMMIT(); CP_WAIT(1); }
        else             { CP_WAIT(0); }
        __syncthreads();

        const uint32_t KHo = TB + cur * 2 * TB;
        const uint32_t VHo = KHo + TB;

        // ---- S = Q K^T (single fp16) ----
        float s[2][8][4];
#pragma unroll
        for (int mm = 0; mm < 2; mm++)
#pragma unroll
            for (int j = 0; j < 8; j++)
#pragma unroll
                for (int c = 0; c < 4; c++) s[mm][j][c] = 0.f;

#pragma unroll
        for (int ks = 0; ks < 4; ks++) {
            const int cb = (ks * 16 + 2 * cq) * 2;
            uint32_t aq[2][4];
#pragma unroll
            for (int mm = 0; mm < 2; mm++) {
                const char* q0 = smem + (arowb + mm * 16) * ROWB + cb;
                aq[mm][0] = *(const uint32_t*)(q0);
                aq[mm][1] = *(const uint32_t*)(q0 + 8 * ROWB);
                aq[mm][2] = *(const uint32_t*)(q0 + 16);
                aq[mm][3] = *(const uint32_t*)(q0 + 8 * ROWB + 16);
            }
#pragma unroll
            for (int j = 0; j < 8; j++) {
                const char* kp = smem + KHo + (krowb + j * 8) * ROWB + cb;
                uint32_t b0 = *(const uint32_t*)(kp);
                uint32_t b1 = *(const uint32_t*)(kp + 16);
#pragma unroll
                for (int mm = 0; mm < 2; mm++) {
                    float* d = s[mm][j];
                    mma_f16(d[0], d[1], d[2], d[3],
                            aq[mm][0], aq[mm][1], aq[mm][2], aq[mm][3], b0, b1);
                }
            }
        }

        // ---- packed exp2 softmax + PV per 16-key chunk ----
#pragma unroll
        for (int t = 0; t < 4; t++) {
            uint32_t ph[2][4];
#pragma unroll
            for (int jj = 0; jj < 2; jj++) {
                const int j = 2 * t + jj;
#pragma unroll
                for (int mm = 0; mm < 2; mm++) {
                    const int blk0 = blk0base + mm * 2;
#pragma unroll
                    for (int half = 0; half < 2; half++) {
                        const u64 mf2 = (j == blk0 + half) ? cI2 : cX2;
                        u64 s2 = pk2(s[mm][j][half * 2], s[mm][j][half * 2 + 1]);
                        u64 x2 = mul2(s2, mf2);
                        u64 t2 = add2(x2, magic2);
                        u64 n2 = add2(t2, nmagic2);
                        u64 f2 = fma2(n2, neg1_2, x2);
                        u64 p2 = fma2(C0, f2, C1);
                        p2 = fma2(p2, f2, C2);
                        p2 = fma2(p2, f2, C3);
                        p2 = fma2(p2, f2, C4);
                        p2 = fma2(p2, f2, C5);
                        p2 = fma2(p2, f2, C6);
                        uint32_t tl = (uint32_t)t2, th = (uint32_t)(t2 >> 32);
                        const uint32_t KC = 0x4B400000u - 127u;
                        uint32_t sl = (tl - KC) << 23;
                        uint32_t sh = (th - KC) << 23;
                        u64 sc2 = ((u64)sh << 32) | (u64)sl;
                        u64 pe = mul2(p2, sc2);
                        lp2[mm][half] = add2(lp2[mm][half], pe);
                        float p0, p1; upk2(pe, p0, p1);
                        __half2 h2 = __floats2half2_rn(p0, p1);
                        ph[mm][jj * 2 + half] = *(uint32_t*)&h2;
                    }
                }
            }
            const uint32_t va0 = sb32 + VHo + (vrow_off + t * 16) * ROWB + vcolB;
#pragma unroll
            for (int jnp = 0; jnp < 4; jnp++) {
                uint32_t v0, v1, v2, v3;
                ldsm4t(v0, v1, v2, v3, va0 + jnp * 32);
#pragma unroll
                for (int mm = 0; mm < 2; mm++) {
                    float* o0 = o[mm][jnp * 2];
                    mma_f16(o0[0], o0[1], o0[2], o0[3],
                            ph[mm][0], ph[mm][1], ph[mm][2], ph[mm][3], v0, v1);
                    float* o1 = o[mm][jnp * 2 + 1];
                    mma_f16(o1[0], o1[1], o1[2], o1[3],
                            ph[mm][0], ph[mm][1], ph[mm][2], ph[mm][3], v2, v3);
                }
            }
        }
        __syncthreads();
    }

    // ---- cross-warp combine ----
    float lpart[2][2];
#pragma unroll
    for (int mm = 0; mm < 2; mm++)
#pragma unroll
        for (int half = 0; half < 2; half++) {
            float a, bb; upk2(lp2[mm][half], a, bb);
            float v = a + bb;
            v += __shfl_xor_sync(0xffffffffu, v, 1);
            v += __shfl_xor_sync(0xffffffffu, v, 2);
            lpart[mm][half] = v;
        }
    float* Ost = (float*)(smem + TB);
    float* Lst = (float*)(smem + TB + 128 * 68 * 4);
    if (wn2 == 1) {
#pragma unroll
        for (int mm = 0; mm < 2; mm++) {
            int row = wm4 * 32 + mm * 16 + r_;
#pragma unroll
            for (int jn = 0; jn < 8; jn++) {
                int col = jn * 8 + 2 * cq;
                *(float2*)&Ost[row * 68 + col]       = make_float2(o[mm][jn][0], o[mm][jn][1]);
                *(float2*)&Ost[(row + 8) * 68 + col] = make_float2(o[mm][jn][2], o[mm][jn][3]);
            }
            if (cq == 0) {
                Lst[row]     = lpart[mm][0];
                Lst[row + 8] = lpart[mm][1];
            }
        }
    }
    __syncthreads();
    if (wn2 == 0) {
#pragma unroll
        for (int mm = 0; mm < 2; mm++) {
            int row = wm4 * 32 + mm * 16 + r_;
            float inv0 = 1.0f / (lpart[mm][0] + Lst[row]);
            float inv1 = 1.0f / (lpart[mm][1] + Lst[row + 8]);
            float* op0 = out + ((size_t)b * T_ + qt * 128 + row) * D_ + h * 64;
            float* op1 = op0 + 8 * D_;
#pragma unroll
            for (int jn = 0; jn < 8; jn++) {
                int col = jn * 8 + 2 * cq;
                float2 a0 = *(float2*)&Ost[row * 68 + col];
                float2 a1 = *(float2*)&Ost[(row + 8) * 68 + col];
                float2 w0 = make_float2((o[mm][jn][0] + a0.x) * inv0,
                                        (o[mm][jn][1] + a0.y) * inv0);
                float2 w1 = make_float2((o[mm][jn][2] + a1.x) * inv1,
                                        (o[mm][jn][3] + a1.y) * inv1);
                *(float2*)&op0[col] = w0;
                *(float2*)&op1[col] = w1;
            }
        }
    }
}

// ---------------------------------------------------------------------------
extern "C" void kernel_launch(void* const* d_in, const int* in_sizes, int n_in,
                              void* d_out, int out_size)
{
    const float* x  = (const float*)d_in[0];
    const float* Wq = (const float*)d_in[1];
    const float* Wk = (const float*)d_in[2];
    const float* Wv = (const float*)d_in[3];
    const float* wp = (const float*)d_in[4];
    float* out = (float*)d_out;

    __half *xh, *xl, *wf;
    cudaGetSymbolAddress((void**)&xh, g_xh);
    cudaGetSymbolAddress((void**)&xl, g_xl);
    cudaGetSymbolAddress((void**)&wf, g_wf);

    cudaFuncSetAttribute(qkv_gemm_mma, cudaFuncAttributeMaxDynamicSharedMemorySize,
                         GEMM_SMEM);
    cudaFuncSetAttribute(palace_attn_tc, cudaFuncAttributeMaxDynamicSharedMemorySize,
                         ATTN_SMEM);

    int n4x = BT_ * D_ / 4;
    convert_split_h<<<(n4x + 255) / 256, 256>>>(x, xh, xl, n4x);
    int n4w = D_ * D_ / 4;
    convert_h<<<(n4w + 255) / 256, 256>>>(Wq, wf,                   n4w);
    convert_h<<<(n4w + 255) / 256, 256>>>(Wk, wf + (size_t)D_ * D_, n4w);
    convert_h<<<(n4w + 255) / 256, 256>>>(Wv, wf + 2ull * D_ * D_,  n4w);

    qkv_gemm_mma<<<dim3(8, 64, 3), 256, GEMM_SMEM>>>();
    palace_attn_tc<<<dim3(T_ / 128, B_ * H_), 256, ATTN_SMEM>>>(wp, out);
}